// round 5
// baseline (speedup 1.0000x reference)
#include <cuda_runtime.h>
#include <cuda_bf16.h>
#include <cstdint>

// Problem constants
#define BB 8
#define NN 128
#define LL 4096
#define DD 1024
#define HH 16
#define DH 64
#define BH (BB*HH)          // 128

typedef __nv_bfloat16 bf16;

// ---------------- scratch (device globals) ----------------
// input splits
__device__ bf16 g_qh[BB*NN*DD], g_ql[BB*NN*DD];       // 2 MB each
__device__ bf16 g_kh[BB*LL*DD], g_kl[BB*LL*DD];       // 64 MB each
__device__ bf16 g_vh[BB*LL*DD], g_vl[BB*LL*DD];       // 64 MB each
__device__ bf16 g_Wh[4*DD*DD], g_Wl[4*DD*DD];         // 8 MB each (Wq,Wk,Wv,Wo)
// projection outputs (planes)
__device__ bf16 g_Qh[BB*NN*DD], g_Ql[BB*NN*DD];
__device__ bf16 g_Kh[BB*LL*DD], g_Kl[BB*LL*DD];
__device__ bf16 g_Vh[BB*LL*DD], g_Vl[BB*LL*DD];
// attention output (planes)
__device__ bf16 g_Oh[BB*NN*DD], g_Ol[BB*NN*DD];

// ---------------- helpers ----------------
__device__ __forceinline__ uint32_t smem_u32(const void* p) {
    uint32_t a;
    asm("{ .reg .u64 t; cvta.to.shared.u64 t, %1; cvt.u32.u64 %0, t; }"
        : "=r"(a) : "l"(p));
    return a;
}
__device__ __forceinline__ uint32_t pk2(float x, float y) {
    uint32_t r;
    asm("cvt.rn.bf16x2.f32 %0, %1, %2;" : "=r"(r) : "f"(y), "f"(x));
    return r;
}
__device__ __forceinline__ uint32_t pk2lo(float x, float y, uint32_t h) {
    float hx = __uint_as_float(h << 16);
    float hy = __uint_as_float(h & 0xFFFF0000u);
    uint32_t r;
    asm("cvt.rn.bf16x2.f32 %0, %1, %2;" : "=r"(r) : "f"(y - hy), "f"(x - hx));
    return r;
}
__device__ __forceinline__ void sts32(uint32_t addr, uint32_t v) {
    asm volatile("st.shared.b32 [%0], %1;" :: "r"(addr), "r"(v) : "memory");
}
__device__ __forceinline__ void cp16(uint32_t s, const void* g) {
    asm volatile("cp.async.cg.shared.global [%0], [%1], 16;" :: "r"(s), "l"(g));
}
#define CP_COMMIT() asm volatile("cp.async.commit_group;" ::: "memory")
#define CP_WAIT0()  asm volatile("cp.async.wait_group 0;" ::: "memory")
#define CP_WAIT1()  asm volatile("cp.async.wait_group 1;" ::: "memory")

#define LDSM4(r, a) \
    asm volatile("ldmatrix.sync.aligned.m8n8.x4.shared.b16 {%0,%1,%2,%3}, [%4];" \
        : "=r"((r)[0]), "=r"((r)[1]), "=r"((r)[2]), "=r"((r)[3]) : "r"(a))
#define LDSM4T(r, a) \
    asm volatile("ldmatrix.sync.aligned.m8n8.x4.trans.shared.b16 {%0,%1,%2,%3}, [%4];" \
        : "=r"((r)[0]), "=r"((r)[1]), "=r"((r)[2]), "=r"((r)[3]) : "r"(a))

#define MMA16816(d, a, b) \
    asm volatile("mma.sync.aligned.m16n8k16.row.col.f32.bf16.bf16.f32 " \
        "{%0,%1,%2,%3}, {%4,%5,%6,%7}, {%8,%9}, {%0,%1,%2,%3};" \
        : "+f"((d)[0]), "+f"((d)[1]), "+f"((d)[2]), "+f"((d)[3]) \
        : "r"((a)[0]), "r"((a)[1]), "r"((a)[2]), "r"((a)[3]), \
          "r"((b)[0]), "r"((b)[1]))

// ---------------- split: fp32 -> bf16 hi/lo planes ---------------------------
__global__ void __launch_bounds__(256)
split_kernel(const float* __restrict__ x, bf16* __restrict__ xh,
             bf16* __restrict__ xl, int n4)
{
    int i = blockIdx.x * blockDim.x + threadIdx.x;
    if (i >= n4) return;
    float4 v = reinterpret_cast<const float4*>(x)[i];
    uint32_t h01 = pk2(v.x, v.y), h23 = pk2(v.z, v.w);
    uint32_t l01 = pk2lo(v.x, v.y, h01), l23 = pk2lo(v.z, v.w, h23);
    reinterpret_cast<uint2*>(xh)[i] = make_uint2(h01, h23);
    reinterpret_cast<uint2*>(xl)[i] = make_uint2(l01, l23);
}

// ---------------- bf16-plane NT GEMM: C = alpha * A @ B^T --------------------
// A planes [M,K] bf16, B planes [N,K] bf16. Tile 128x64, BK=64 bf16.
// PLANE_OUT: write Ch/Cl bf16 planes; else fp32 Cf.
#define GPK 144
#define GA_SZ (128*GPK)     // 18432
#define GB_SZ (64*GPK)      // 9216
#define GSTAGE (2*GA_SZ + 2*GB_SZ)  // 55296
#define GEMM_SMEM (2*GSTAGE)        // 110592

template<bool PLANE_OUT>
__global__ void __launch_bounds__(256, 2)
gemm_planes(const bf16* __restrict__ Ah, const bf16* __restrict__ Al,
            const bf16* __restrict__ Bh, const bf16* __restrict__ Bl,
            float* __restrict__ Cf, bf16* __restrict__ Ch, bf16* __restrict__ Cl,
            int K, float alpha)
{
    extern __shared__ char smem[];
    const uint32_t sb = smem_u32(smem);
    const int tid = threadIdx.x, wid = tid >> 5, lane = tid & 31;
    const int wm = wid & 3, wn = wid >> 2;
    const int m0 = blockIdx.y * 128, n0 = blockIdx.x * 64;

    float acc[2][4][4];
#pragma unroll
    for (int i = 0; i < 2; i++)
#pragma unroll
        for (int j = 0; j < 4; j++)
#pragma unroll
            for (int q = 0; q < 4; q++) acc[i][j][q] = 0.f;

    const int ar = tid >> 1, as2 = (tid & 1) * 4;
    const int br = tid >> 2, bs2 = (tid & 3) * 2;

    auto prefetch = [&](int c, int st) {
        const uint32_t base = sb + st * GSTAGE;
        const long k0 = (long)c * 64;
        const bf16* Ahp = Ah + (long)(m0 + ar) * DD + k0;
        const bf16* Alp = Al + (long)(m0 + ar) * DD + k0;
        uint32_t ro = base + ar * GPK;
#pragma unroll
        for (int s = 0; s < 4; s++) {
            cp16(ro + (as2 + s) * 16, Ahp + (as2 + s) * 8);
            cp16(ro + GA_SZ + (as2 + s) * 16, Alp + (as2 + s) * 8);
        }
        const bf16* Bhp = Bh + (long)(n0 + br) * DD + k0;
        const bf16* Blp = Bl + (long)(n0 + br) * DD + k0;
        uint32_t rbo = base + 2 * GA_SZ + br * GPK;
#pragma unroll
        for (int s = 0; s < 2; s++) {
            cp16(rbo + (bs2 + s) * 16, Bhp + (bs2 + s) * 8);
            cp16(rbo + GB_SZ + (bs2 + s) * 16, Blp + (bs2 + s) * 8);
        }
        CP_COMMIT();
    };

    const uint32_t lmo = (uint32_t)((lane & 15) * GPK + ((lane >> 4) << 4));

    auto compute = [&](int st) {
        const uint32_t base = sb + st * GSTAGE;
        const uint32_t bbase = base + 2 * GA_SZ;
#pragma unroll
        for (int ks = 0; ks < 4; ks++) {
            uint32_t ah[2][4], al[2][4];
#pragma unroll
            for (int mt = 0; mt < 2; mt++) {
                uint32_t ad = base + (uint32_t)((wm * 32 + mt * 16) * GPK + ks * 32) + lmo;
                LDSM4(ah[mt], ad);
                LDSM4(al[mt], ad + GA_SZ);
            }
            uint32_t bhp[4][2], blp[4][2];
#pragma unroll
            for (int j = 0; j < 2; j++) {
                uint32_t bd = bbase + (uint32_t)((wn * 32 + j * 16) * GPK + ks * 32) + lmo;
                uint32_t t[4];
                LDSM4(t, bd);
                bhp[2*j][0] = t[0]; bhp[2*j][1] = t[2];
                bhp[2*j+1][0] = t[1]; bhp[2*j+1][1] = t[3];
                LDSM4(t, bd + GB_SZ);
                blp[2*j][0] = t[0]; blp[2*j][1] = t[2];
                blp[2*j+1][0] = t[1]; blp[2*j+1][1] = t[3];
            }
#pragma unroll
            for (int mt = 0; mt < 2; mt++)
#pragma unroll
                for (int nt = 0; nt < 4; nt++) {
                    MMA16816(acc[mt][nt], ah[mt], bhp[nt]);
                    MMA16816(acc[mt][nt], ah[mt], blp[nt]);
                    MMA16816(acc[mt][nt], al[mt], bhp[nt]);
                }
        }
    };

    const int NC = K >> 6;
    prefetch(0, 0);
    for (int c = 0; c < NC; c++) {
        if (c + 1 < NC) { prefetch(c + 1, (c + 1) & 1); CP_WAIT1(); }
        else CP_WAIT0();
        __syncthreads();
        compute(c & 1);
        __syncthreads();
    }

#pragma unroll
    for (int mt = 0; mt < 2; mt++) {
        int mr = m0 + wm * 32 + mt * 16 + (lane >> 2);
#pragma unroll
        for (int nt = 0; nt < 4; nt++) {
            int col = n0 + wn * 32 + nt * 8 + (lane & 3) * 2;
            float a0 = acc[mt][nt][0] * alpha, a1 = acc[mt][nt][1] * alpha;
            float a2 = acc[mt][nt][2] * alpha, a3 = acc[mt][nt][3] * alpha;
            if (PLANE_OUT) {
                uint32_t h0 = pk2(a0, a1), l0 = pk2lo(a0, a1, h0);
                uint32_t h1 = pk2(a2, a3), l1 = pk2lo(a2, a3, h1);
                *reinterpret_cast<uint32_t*>(&Ch[(long)mr * DD + col]) = h0;
                *reinterpret_cast<uint32_t*>(&Cl[(long)mr * DD + col]) = l0;
                *reinterpret_cast<uint32_t*>(&Ch[(long)(mr + 8) * DD + col]) = h1;
                *reinterpret_cast<uint32_t*>(&Cl[(long)(mr + 8) * DD + col]) = l1;
            } else {
                *reinterpret_cast<float2*>(&Cf[(long)mr * DD + col]) = make_float2(a0, a1);
                *reinterpret_cast<float2*>(&Cf[(long)(mr + 8) * DD + col]) = make_float2(a2, a3);
            }
        }
    }
}

// ---------------- fused attention -------------------------------------------
// One CTA per (b,h). S = Q@K^T chunkwise (Q pre-scaled); exact column softmax
// over n=128 (no max subtraction; |S| < ~1.5); P@[V | ones]; epilogue divides
// by rowsum; writes O planes.
#define FPK 144
#define FPV 176
#define QH_O 0
#define QL_O 18432
#define KP_O 36864           // KH0,KL0,KH1,KL1 each 18432
#define VP_O 110592          // VH0,VL0,VH1,VL1 each 22528
#define CST_O 200704
#define FUSED_SMEM (CST_O + (8*128+128)*4)   // 205312

__global__ void __launch_bounds__(256, 1)
fused_attn(const bf16* __restrict__ Qh, const bf16* __restrict__ Ql,
           const bf16* __restrict__ Kh, const bf16* __restrict__ Kl,
           const bf16* __restrict__ Vh, const bf16* __restrict__ Vl,
           bf16* __restrict__ Oh, bf16* __restrict__ Ol)
{
    extern __shared__ char smem[];
    const uint32_t sb = smem_u32(smem);
    float* cst = reinterpret_cast<float*>(smem + CST_O);

    const int tid = threadIdx.x, wid = tid >> 5, lane = tid & 31;
    const int bh = blockIdx.x, b = bh >> 4, hh = bh & 15;
    const bf16* Qhp = Qh + (long)b * NN * DD + hh * DH;
    const bf16* Qlp = Ql + (long)b * NN * DD + hh * DH;
    const bf16* Khp = Kh + (long)b * LL * DD + hh * DH;
    const bf16* Klp = Kl + (long)b * LL * DD + hh * DH;
    const bf16* Vhp = Vh + (long)b * LL * DD + hh * DH;
    const bf16* Vlp = Vl + (long)b * LL * DD + hh * DH;

    const uint32_t QHI = sb + QH_O, QLO = sb + QL_O;

    // init ones cols (64..71) + pad (72..79) in both V stages, both planes
    if (tid < 128) {
        int r = tid;
#pragma unroll
        for (int st = 0; st < 2; st++) {
            uint32_t vh = sb + VP_O + st * 45056 + (uint32_t)r * FPV;
            uint32_t vl = vh + 22528;
#pragma unroll
            for (int cb = 0; cb < 4; cb++) {
                sts32(vh + 128 + cb * 4, 0x3F803F80u);
                sts32(vl + 128 + cb * 4, 0u);
                sts32(vh + 144 + cb * 4, 0u);
                sts32(vl + 144 + cb * 4, 0u);
            }
        }
    }

    const int qr = tid >> 1, qs = (tid & 1) * 4;
    // Q load (group 0, together with chunk 0)
#pragma unroll
    for (int s = 0; s < 4; s++) {
        cp16(QHI + qr * FPK + (qs + s) * 16, Qhp + (long)qr * DD + (qs + s) * 8);
        cp16(QLO + qr * FPK + (qs + s) * 16, Qlp + (long)qr * DD + (qs + s) * 8);
    }

    auto prefetch = [&](int c, int st) {
        const long l0 = (long)c * 128;
        const uint32_t kh = sb + KP_O + st * 36864;
        const uint32_t kl = kh + 18432;
        const uint32_t vh = sb + VP_O + st * 45056;
        const uint32_t vl = vh + 22528;
#pragma unroll
        for (int s = 0; s < 4; s++) {
            cp16(kh + qr * FPK + (qs + s) * 16, Khp + (l0 + qr) * DD + (qs + s) * 8);
            cp16(kl + qr * FPK + (qs + s) * 16, Klp + (l0 + qr) * DD + (qs + s) * 8);
            cp16(vh + qr * FPV + (qs + s) * 16, Vhp + (l0 + qr) * DD + (qs + s) * 8);
            cp16(vl + qr * FPV + (qs + s) * 16, Vlp + (l0 + qr) * DD + (qs + s) * 8);
        }
        CP_COMMIT();
    };

    float acc2[9][4];
#pragma unroll
    for (int i = 0; i < 9; i++)
#pragma unroll
        for (int j = 0; j < 4; j++) acc2[i][j] = 0.f;

    const int mrow = wid * 16;
    const uint32_t lqk = (uint32_t)((lane & 15) * FPK + ((lane >> 4) << 4));
    const uint32_t lv  = (uint32_t)((lane & 15) * FPV + ((lane >> 4) << 4));

    prefetch(0, 0);   // commits group 0 incl. Q

    for (int c = 0; c < 32; c++) {
        const int st = c & 1;
        if (c + 1 < 32) { prefetch(c + 1, st ^ 1); CP_WAIT1(); }
        else CP_WAIT0();
        __syncthreads();

        const uint32_t KHI = sb + KP_O + st * 36864;
        const uint32_t KLO = KHI + 18432;
        const uint32_t VHI = sb + VP_O + st * 45056;
        const uint32_t VLO = VHI + 22528;

        // ---- MMA1: S fragments
        float acc1[16][4];
#pragma unroll
        for (int i = 0; i < 16; i++)
#pragma unroll
            for (int j = 0; j < 4; j++) acc1[i][j] = 0.f;

#pragma unroll
        for (int ks = 0; ks < 4; ks++) {
            uint32_t ah[4], al[4];
            LDSM4(ah, QHI + (uint32_t)(mrow * FPK + ks * 32) + lqk);
            LDSM4(al, QLO + (uint32_t)(mrow * FPK + ks * 32) + lqk);
#pragma unroll
            for (int nt2 = 0; nt2 < 8; nt2++) {
                uint32_t th[4], tl[4];
                LDSM4(th, KHI + (uint32_t)(nt2 * 16 * FPK + ks * 32) + lqk);
                LDSM4(tl, KLO + (uint32_t)(nt2 * 16 * FPK + ks * 32) + lqk);
                uint32_t b0h[2] = {th[0], th[2]}, b1h[2] = {th[1], th[3]};
                uint32_t b0l[2] = {tl[0], tl[2]}, b1l[2] = {tl[1], tl[3]};
                MMA16816(acc1[2*nt2],   ah, b0h);
                MMA16816(acc1[2*nt2],   ah, b0l);
                MMA16816(acc1[2*nt2],   al, b0h);
                MMA16816(acc1[2*nt2+1], ah, b1h);
                MMA16816(acc1[2*nt2+1], ah, b1l);
                MMA16816(acc1[2*nt2+1], al, b1h);
            }
        }

        // ---- exp (no max needed: |S| < ~1.5) + column sum over n
#pragma unroll
        for (int nt = 0; nt < 16; nt++) {
            acc1[nt][0] = __expf(acc1[nt][0]);
            acc1[nt][1] = __expf(acc1[nt][1]);
            acc1[nt][2] = __expf(acc1[nt][2]);
            acc1[nt][3] = __expf(acc1[nt][3]);
            float s0 = acc1[nt][0] + acc1[nt][2];
            float s1 = acc1[nt][1] + acc1[nt][3];
            s0 += __shfl_xor_sync(0xffffffffu, s0, 4);
            s0 += __shfl_xor_sync(0xffffffffu, s0, 8);
            s0 += __shfl_xor_sync(0xffffffffu, s0, 16);
            s1 += __shfl_xor_sync(0xffffffffu, s1, 4);
            s1 += __shfl_xor_sync(0xffffffffu, s1, 8);
            s1 += __shfl_xor_sync(0xffffffffu, s1, 16);
            if (lane < 4) {
                cst[wid * 128 + nt * 8 + lane * 2]     = s0;
                cst[wid * 128 + nt * 8 + lane * 2 + 1] = s1;
            }
        }
        __syncthreads();
        if (tid < 128) {
            float s = 0.f;
#pragma unroll
            for (int w = 0; w < 8; w++) s += cst[w * 128 + tid];
            cst[1024 + tid] = 1.f / s;
        }
        __syncthreads();
#pragma unroll
        for (int nt = 0; nt < 16; nt++) {
            float2 iv = *reinterpret_cast<const float2*>(
                &cst[1024 + nt * 8 + (lane & 3) * 2]);
            acc1[nt][0] *= iv.x; acc1[nt][1] *= iv.y;
            acc1[nt][2] *= iv.x; acc1[nt][3] *= iv.y;
        }

        // ---- MMA2: acc2 += P @ [V | ones]
#pragma unroll
        for (int ks2 = 0; ks2 < 8; ks2++) {
            const float* p0 = acc1[2*ks2];
            const float* p1 = acc1[2*ks2+1];
            uint32_t pah[4], pal[4];
            pah[0] = pk2(p0[0], p0[1]); pal[0] = pk2lo(p0[0], p0[1], pah[0]);
            pah[1] = pk2(p0[2], p0[3]); pal[1] = pk2lo(p0[2], p0[3], pah[1]);
            pah[2] = pk2(p1[0], p1[1]); pal[2] = pk2lo(p1[0], p1[1], pah[2]);
            pah[3] = pk2(p1[2], p1[3]); pal[3] = pk2lo(p1[2], p1[3], pah[3]);
#pragma unroll
            for (int nt2 = 0; nt2 < 5; nt2++) {
                uint32_t th[4], tl[4];
                LDSM4T(th, VHI + (uint32_t)(ks2 * 16 * FPV + nt2 * 32) + lv);
                LDSM4T(tl, VLO + (uint32_t)(ks2 * 16 * FPV + nt2 * 32) + lv);
                uint32_t b0h[2] = {th[0], th[1]}, b0l[2] = {tl[0], tl[1]};
                MMA16816(acc2[2*nt2], pah, b0h);
                MMA16816(acc2[2*nt2], pah, b0l);
                MMA16816(acc2[2*nt2], pal, b0h);
                if (nt2 < 4) {
                    uint32_t b1h[2] = {th[2], th[3]}, b1l[2] = {tl[2], tl[3]};
                    MMA16816(acc2[2*nt2+1], pah, b1h);
                    MMA16816(acc2[2*nt2+1], pah, b1l);
                    MMA16816(acc2[2*nt2+1], pal, b1h);
                }
            }
        }
        __syncthreads();
    }

    // ---- epilogue: divide by rowsum (ones column), write O planes
    float rs0 = __shfl_sync(0xffffffffu, acc2[8][0], lane & ~3);
    float rs2 = __shfl_sync(0xffffffffu, acc2[8][2], lane & ~3);
    float i0 = 1.f / rs0, i2 = 1.f / rs2;
    int r0 = mrow + (lane >> 2);
    long ob = (long)b * NN * DD + hh * DH;
#pragma unroll
    for (int nt = 0; nt < 8; nt++) {
        int cc = nt * 8 + (lane & 3) * 2;
        float a0 = acc2[nt][0] * i0, a1 = acc2[nt][1] * i0;
        float a2 = acc2[nt][2] * i2, a3 = acc2[nt][3] * i2;
        uint32_t h0 = pk2(a0, a1), l0 = pk2lo(a0, a1, h0);
        uint32_t h1 = pk2(a2, a3), l1 = pk2lo(a2, a3, h1);
        *reinterpret_cast<uint32_t*>(&Oh[ob + (long)r0 * DD + cc]) = h0;
        *reinterpret_cast<uint32_t*>(&Ol[ob + (long)r0 * DD + cc]) = l0;
        *reinterpret_cast<uint32_t*>(&Oh[ob + (long)(r0 + 8) * DD + cc]) = h1;
        *reinterpret_cast<uint32_t*>(&Ol[ob + (long)(r0 + 8) * DD + cc]) = l1;
    }
}

// ---------------- launch ----------------------------------------------------
extern "C" void kernel_launch(void* const* d_in, const int* in_sizes, int n_in,
                              void* d_out, int out_size)
{
    const float* q  = (const float*)d_in[0];
    const float* k  = (const float*)d_in[1];
    const float* v  = (const float*)d_in[2];
    const float* Wq = (const float*)d_in[3];
    const float* Wk = (const float*)d_in[4];
    const float* Wv = (const float*)d_in[5];
    const float* Wo = (const float*)d_in[6];
    float* out = (float*)d_out;

    bf16 *qh, *ql, *kh, *kl, *vh, *vl, *Wh, *Wl;
    bf16 *Qh, *Ql, *Kh, *Kl, *Vh, *Vl, *Oh, *Ol;
    cudaGetSymbolAddress((void**)&qh, g_qh); cudaGetSymbolAddress((void**)&ql, g_ql);
    cudaGetSymbolAddress((void**)&kh, g_kh); cudaGetSymbolAddress((void**)&kl, g_kl);
    cudaGetSymbolAddress((void**)&vh, g_vh); cudaGetSymbolAddress((void**)&vl, g_vl);
    cudaGetSymbolAddress((void**)&Wh, g_Wh); cudaGetSymbolAddress((void**)&Wl, g_Wl);
    cudaGetSymbolAddress((void**)&Qh, g_Qh); cudaGetSymbolAddress((void**)&Ql, g_Ql);
    cudaGetSymbolAddress((void**)&Kh, g_Kh); cudaGetSymbolAddress((void**)&Kl, g_Kl);
    cudaGetSymbolAddress((void**)&Vh, g_Vh); cudaGetSymbolAddress((void**)&Vl, g_Vl);
    cudaGetSymbolAddress((void**)&Oh, g_Oh); cudaGetSymbolAddress((void**)&Ol, g_Ol);

    cudaFuncSetAttribute((const void*)gemm_planes<true>,
                         cudaFuncAttributeMaxDynamicSharedMemorySize, GEMM_SMEM);
    cudaFuncSetAttribute((const void*)gemm_planes<false>,
                         cudaFuncAttributeMaxDynamicSharedMemorySize, GEMM_SMEM);
    cudaFuncSetAttribute((const void*)fused_attn,
                         cudaFuncAttributeMaxDynamicSharedMemorySize, FUSED_SMEM);

    const int WN4 = DD * DD / 4;      // 262144
    const int QN4 = BB * NN * DD / 4; // 262144
    const int KN4 = BB * LL * DD / 4; // 8388608

    // splits
    split_kernel<<<QN4 / 256, 256>>>(q, qh, ql, QN4);
    split_kernel<<<KN4 / 256, 256>>>(k, kh, kl, KN4);
    split_kernel<<<KN4 / 256, 256>>>(v, vh, vl, KN4);
    split_kernel<<<WN4 / 256, 256>>>(Wq, Wh + 0*DD*DD, Wl + 0*DD*DD, WN4);
    split_kernel<<<WN4 / 256, 256>>>(Wk, Wh + 1*DD*DD, Wl + 1*DD*DD, WN4);
    split_kernel<<<WN4 / 256, 256>>>(Wv, Wh + 2*DD*DD, Wl + 2*DD*DD, WN4);
    split_kernel<<<WN4 / 256, 256>>>(Wo, Wh + 3*DD*DD, Wl + 3*DD*DD, WN4);

    const float SCALE = 0.03125f;  // D^-0.5, folded into Q projection

    // projections (plane outputs)
    gemm_planes<true><<<dim3(16, (BB*NN)/128), 256, GEMM_SMEM>>>(
        qh, ql, Wh + 0*DD*DD, Wl + 0*DD*DD, nullptr, Qh, Ql, DD, SCALE);
    gemm_planes<true><<<dim3(16, (BB*LL)/128), 256, GEMM_SMEM>>>(
        kh, kl, Wh + 1*DD*DD, Wl + 1*DD*DD, nullptr, Kh, Kl, DD, 1.f);
    gemm_planes<true><<<dim3(16, (BB*LL)/128), 256, GEMM_SMEM>>>(
        vh, vl, Wh + 2*DD*DD, Wl + 2*DD*DD, nullptr, Vh, Vl, DD, 1.f);

    // fused: scores + inverted softmax + L1 renorm + AV -> O planes
    fused_attn<<<BH, 256, FUSED_SMEM>>>(Qh, Ql, Kh, Kl, Vh, Vl, Oh, Ol);

    // output projection (fp32 out)
    gemm_planes<false><<<dim3(16, (BB*NN)/128), 256, GEMM_SMEM>>>(
        Oh, Ol, Wh + 3*DD*DD, Wl + 3*DD*DD, out, nullptr, nullptr, DD, 1.f);
}

// round 6
// speedup vs baseline: 1.1966x; 1.1966x over previous
#include <cuda_runtime.h>
#include <cuda_bf16.h>
#include <cstdint>

// Problem constants
#define BB 8
#define NN 128
#define LL 4096
#define DD 1024
#define HH 16
#define DH 64
#define BH (BB*HH)          // 128

typedef __nv_bfloat16 bf16;

// ---------------- scratch (device globals) ----------------
__device__ bf16 g_qh[BB*NN*DD], g_ql[BB*NN*DD];
__device__ bf16 g_kh[BB*LL*DD], g_kl[BB*LL*DD];
__device__ bf16 g_vh[BB*LL*DD], g_vl[BB*LL*DD];
__device__ bf16 g_Wh[4*DD*DD], g_Wl[4*DD*DD];
__device__ bf16 g_Qh[BB*NN*DD], g_Ql[BB*NN*DD];
__device__ bf16 g_Kh[BB*LL*DD], g_Kl[BB*LL*DD];
__device__ bf16 g_Vh[BB*LL*DD], g_Vl[BB*LL*DD];
__device__ bf16 g_Oh[BB*NN*DD], g_Ol[BB*NN*DD];

// ---------------- helpers ----------------
__device__ __forceinline__ uint32_t smem_u32(const void* p) {
    uint32_t a;
    asm("{ .reg .u64 t; cvta.to.shared.u64 t, %1; cvt.u32.u64 %0, t; }"
        : "=r"(a) : "l"(p));
    return a;
}
__device__ __forceinline__ uint32_t pk2(float x, float y) {
    uint32_t r;
    asm("cvt.rn.bf16x2.f32 %0, %1, %2;" : "=r"(r) : "f"(y), "f"(x));
    return r;
}
__device__ __forceinline__ uint32_t pk2lo(float x, float y, uint32_t h) {
    float hx = __uint_as_float(h << 16);
    float hy = __uint_as_float(h & 0xFFFF0000u);
    uint32_t r;
    asm("cvt.rn.bf16x2.f32 %0, %1, %2;" : "=r"(r) : "f"(y - hy), "f"(x - hx));
    return r;
}
__device__ __forceinline__ void sts32(uint32_t addr, uint32_t v) {
    asm volatile("st.shared.b32 [%0], %1;" :: "r"(addr), "r"(v) : "memory");
}
__device__ __forceinline__ void sts128(uint32_t addr, uint4 v) {
    asm volatile("st.shared.v4.b32 [%0], {%1,%2,%3,%4};"
                 :: "r"(addr), "r"(v.x), "r"(v.y), "r"(v.z), "r"(v.w) : "memory");
}
__device__ __forceinline__ void cp16(uint32_t s, const void* g) {
    asm volatile("cp.async.cg.shared.global [%0], [%1], 16;" :: "r"(s), "l"(g));
}
#define CP_COMMIT() asm volatile("cp.async.commit_group;" ::: "memory")
#define CP_WAIT0()  asm volatile("cp.async.wait_group 0;" ::: "memory")

#define LDSM4(r, a) \
    asm volatile("ldmatrix.sync.aligned.m8n8.x4.shared.b16 {%0,%1,%2,%3}, [%4];" \
        : "=r"((r)[0]), "=r"((r)[1]), "=r"((r)[2]), "=r"((r)[3]) : "r"(a))
#define LDSM4T(r, a) \
    asm volatile("ldmatrix.sync.aligned.m8n8.x4.trans.shared.b16 {%0,%1,%2,%3}, [%4];" \
        : "=r"((r)[0]), "=r"((r)[1]), "=r"((r)[2]), "=r"((r)[3]) : "r"(a))

#define MMA16816(d, a, b) \
    asm volatile("mma.sync.aligned.m16n8k16.row.col.f32.bf16.bf16.f32 " \
        "{%0,%1,%2,%3}, {%4,%5,%6,%7}, {%8,%9}, {%0,%1,%2,%3};" \
        : "+f"((d)[0]), "+f"((d)[1]), "+f"((d)[2]), "+f"((d)[3]) \
        : "r"((a)[0]), "r"((a)[1]), "r"((a)[2]), "r"((a)[3]), \
          "r"((b)[0]), "r"((b)[1]))

// ---------------- split: fp32 -> bf16 hi/lo planes ---------------------------
__global__ void __launch_bounds__(256)
split_kernel(const float* __restrict__ x, bf16* __restrict__ xh,
             bf16* __restrict__ xl, int n4)
{
    int i = blockIdx.x * blockDim.x + threadIdx.x;
    if (i >= n4) return;
    float4 v = reinterpret_cast<const float4*>(x)[i];
    uint32_t h01 = pk2(v.x, v.y), h23 = pk2(v.z, v.w);
    uint32_t l01 = pk2lo(v.x, v.y, h01), l23 = pk2lo(v.z, v.w, h23);
    reinterpret_cast<uint2*>(xh)[i] = make_uint2(h01, h23);
    reinterpret_cast<uint2*>(xl)[i] = make_uint2(l01, l23);
}

// ---------------- bf16-plane NT GEMM: C = alpha * A @ B^T --------------------
// Tile 128x64, BK=32 bf16. R4-style pipeline: LDG->regs, compute, STS, sync.
#define PPK 80
#define PA_SZ (128*PPK)             // 10240
#define PB_SZ (64*PPK)              // 5120
#define PSTAGE (2*PA_SZ + 2*PB_SZ)  // 30720
#define PSMEM  (2*PSTAGE)           // 61440

template<bool PLANE_OUT>
__global__ void __launch_bounds__(256, 2)
gemm_planes(const bf16* __restrict__ Ah, const bf16* __restrict__ Al,
            const bf16* __restrict__ Bh, const bf16* __restrict__ Bl,
            float* __restrict__ Cf, bf16* __restrict__ Ch, bf16* __restrict__ Cl,
            int K, float alpha)
{
    extern __shared__ char smem[];
    const uint32_t sb = smem_u32(smem);
    const int tid = threadIdx.x, wid = tid >> 5, lane = tid & 31;
    const int wm = wid & 3, wn = wid >> 2;
    const int m0 = blockIdx.y * 128, n0 = blockIdx.x * 64;

    float acc[2][4][4];
#pragma unroll
    for (int i = 0; i < 2; i++)
#pragma unroll
        for (int j = 0; j < 4; j++)
#pragma unroll
            for (int q = 0; q < 4; q++) acc[i][j][q] = 0.f;

    uint4 rah[2], ral[2], rbh, rbl;
    const int br = tid >> 2, bs = tid & 3;   // B unit; A units tid, tid+256

    auto ldg = [&](int c) {
        const long k0 = (long)c * 32;
#pragma unroll
        for (int i = 0; i < 2; i++) {
            int u = tid + (i << 8);
            int r = u >> 2, s = u & 3;
            long off = (long)(m0 + r) * DD + k0 + s * 8;
            rah[i] = *reinterpret_cast<const uint4*>(Ah + off);
            ral[i] = *reinterpret_cast<const uint4*>(Al + off);
        }
        long boff = (long)(n0 + br) * DD + k0 + bs * 8;
        rbh = *reinterpret_cast<const uint4*>(Bh + boff);
        rbl = *reinterpret_cast<const uint4*>(Bl + boff);
    };
    auto sts_stage = [&](int st) {
        const uint32_t base = sb + st * PSTAGE;
#pragma unroll
        for (int i = 0; i < 2; i++) {
            int u = tid + (i << 8);
            int r = u >> 2, s = u & 3;
            uint32_t o = (uint32_t)(r * PPK + s * 16);
            sts128(base + o, rah[i]);
            sts128(base + PA_SZ + o, ral[i]);
        }
        uint32_t bo = (uint32_t)(br * PPK + bs * 16);
        sts128(base + 2 * PA_SZ + bo, rbh);
        sts128(base + 2 * PA_SZ + PB_SZ + bo, rbl);
    };

    const uint32_t lmo = (uint32_t)((lane & 15) * PPK + ((lane >> 4) << 4));

    auto compute = [&](int st) {
        const uint32_t abase = sb + st * PSTAGE;
        const uint32_t bbase = abase + 2 * PA_SZ;
#pragma unroll
        for (int ks = 0; ks < 2; ks++) {
            uint32_t ah[2][4], al[2][4];
#pragma unroll
            for (int mt = 0; mt < 2; mt++) {
                uint32_t ad = abase + (uint32_t)((wm * 32 + mt * 16) * PPK + ks * 32) + lmo;
                LDSM4(ah[mt], ad);
                LDSM4(al[mt], ad + PA_SZ);
            }
            uint32_t bhp[4][2], blp[4][2];
#pragma unroll
            for (int j = 0; j < 2; j++) {
                uint32_t bd = bbase + (uint32_t)((wn * 32 + j * 16) * PPK + ks * 32) + lmo;
                uint32_t t[4];
                LDSM4(t, bd);
                bhp[2*j][0] = t[0]; bhp[2*j][1] = t[2];
                bhp[2*j+1][0] = t[1]; bhp[2*j+1][1] = t[3];
                LDSM4(t, bd + PB_SZ);
                blp[2*j][0] = t[0]; blp[2*j][1] = t[2];
                blp[2*j+1][0] = t[1]; blp[2*j+1][1] = t[3];
            }
#pragma unroll
            for (int mt = 0; mt < 2; mt++)
#pragma unroll
                for (int nt = 0; nt < 4; nt++) {
                    MMA16816(acc[mt][nt], ah[mt], bhp[nt]);
                    MMA16816(acc[mt][nt], ah[mt], blp[nt]);
                    MMA16816(acc[mt][nt], al[mt], bhp[nt]);
                }
        }
    };

    const int NC = K >> 5;
    ldg(0);
    sts_stage(0);
    __syncthreads();

    for (int c = 0; c < NC; c++) {
        if (c + 1 < NC) ldg(c + 1);
        compute(c & 1);
        if (c + 1 < NC) sts_stage((c + 1) & 1);
        __syncthreads();
    }

#pragma unroll
    for (int mt = 0; mt < 2; mt++) {
        int mr = m0 + wm * 32 + mt * 16 + (lane >> 2);
#pragma unroll
        for (int nt = 0; nt < 4; nt++) {
            int col = n0 + wn * 32 + nt * 8 + (lane & 3) * 2;
            float a0 = acc[mt][nt][0] * alpha, a1 = acc[mt][nt][1] * alpha;
            float a2 = acc[mt][nt][2] * alpha, a3 = acc[mt][nt][3] * alpha;
            if (PLANE_OUT) {
                uint32_t h0 = pk2(a0, a1), l0 = pk2lo(a0, a1, h0);
                uint32_t h1 = pk2(a2, a3), l1 = pk2lo(a2, a3, h1);
                *reinterpret_cast<uint32_t*>(&Ch[(long)mr * DD + col]) = h0;
                *reinterpret_cast<uint32_t*>(&Cl[(long)mr * DD + col]) = l0;
                *reinterpret_cast<uint32_t*>(&Ch[(long)(mr + 8) * DD + col]) = h1;
                *reinterpret_cast<uint32_t*>(&Cl[(long)(mr + 8) * DD + col]) = l1;
            } else {
                *reinterpret_cast<float2*>(&Cf[(long)mr * DD + col]) = make_float2(a0, a1);
                *reinterpret_cast<float2*>(&Cf[(long)(mr + 8) * DD + col]) = make_float2(a2, a3);
            }
        }
    }
}

// ---------------- fused attention -------------------------------------------
// One CTA per (b,h). S = Q@K^T chunkwise (Q pre-scaled); exact column softmax
// over n=128 (no max subtraction; |S| < ~1.6); P@[V|ones]; divide by rowsum.
#define FPK 144
#define FPV 176
#define QH_O 0
#define QL_O 18432
#define KP_O 36864            // 2 stages x (hi 18432 + lo 18432)
#define VP_O 110592           // 2 stages x (hi 22528 + lo 22528)
#define CST_O 200704
#define FUSED_SMEM (CST_O + (8*128+128)*4)   // 205312

__global__ void __launch_bounds__(256, 1)
fused_attn(const bf16* __restrict__ Qh, const bf16* __restrict__ Ql,
           const bf16* __restrict__ Kh, const bf16* __restrict__ Kl,
           const bf16* __restrict__ Vh, const bf16* __restrict__ Vl,
           bf16* __restrict__ Oh, bf16* __restrict__ Ol)
{
    extern __shared__ char smem[];
    const uint32_t sb = smem_u32(smem);
    float* cst = reinterpret_cast<float*>(smem + CST_O);

    const int tid = threadIdx.x, wid = tid >> 5, lane = tid & 31;
    const int bh = blockIdx.x, b = bh >> 4, hh = bh & 15;
    const bf16* Qhp = Qh + (long)b * NN * DD + hh * DH;
    const bf16* Qlp = Ql + (long)b * NN * DD + hh * DH;
    const bf16* Khp = Kh + (long)b * LL * DD + hh * DH;
    const bf16* Klp = Kl + (long)b * LL * DD + hh * DH;
    const bf16* Vhp = Vh + (long)b * LL * DD + hh * DH;
    const bf16* Vlp = Vl + (long)b * LL * DD + hh * DH;

    const uint32_t QHI = sb + QH_O, QLO = sb + QL_O;

    // init ones cols (bytes 128..143) + pad (144..159) in both V stages/planes
    if (tid < 128) {
#pragma unroll
        for (int st = 0; st < 2; st++) {
            uint32_t vh = sb + VP_O + st * 45056 + (uint32_t)tid * FPV;
            uint32_t vl = vh + 22528;
#pragma unroll
            for (int cb = 0; cb < 4; cb++) {
                sts32(vh + 128 + cb * 4, 0x3F803F80u);
                sts32(vl + 128 + cb * 4, 0u);
                sts32(vh + 144 + cb * 4, 0u);
                sts32(vl + 144 + cb * 4, 0u);
            }
        }
    }

    const int qr = tid >> 1, qs = (tid & 1) * 4;
#pragma unroll
    for (int s = 0; s < 4; s++) {
        cp16(QHI + qr * FPK + (qs + s) * 16, Qhp + (long)qr * DD + (qs + s) * 8);
        cp16(QLO + qr * FPK + (qs + s) * 16, Qlp + (long)qr * DD + (qs + s) * 8);
    }

    auto prefetch = [&](int c, int st) {
        const long l0 = (long)c * 128;
        const uint32_t kh = sb + KP_O + st * 36864;
        const uint32_t kl = kh + 18432;
        const uint32_t vh = sb + VP_O + st * 45056;
        const uint32_t vl = vh + 22528;
#pragma unroll
        for (int s = 0; s < 4; s++) {
            cp16(kh + qr * FPK + (qs + s) * 16, Khp + (l0 + qr) * DD + (qs + s) * 8);
            cp16(kl + qr * FPK + (qs + s) * 16, Klp + (l0 + qr) * DD + (qs + s) * 8);
            cp16(vh + qr * FPV + (qs + s) * 16, Vhp + (l0 + qr) * DD + (qs + s) * 8);
            cp16(vl + qr * FPV + (qs + s) * 16, Vlp + (l0 + qr) * DD + (qs + s) * 8);
        }
        CP_COMMIT();
    };

    float acc2[9][4];
#pragma unroll
    for (int i = 0; i < 9; i++)
#pragma unroll
        for (int j = 0; j < 4; j++) acc2[i][j] = 0.f;

    const int mrow = wid * 16;
    const uint32_t lqk = (uint32_t)((lane & 15) * FPK + ((lane >> 4) << 4));
    const uint32_t lv  = (uint32_t)((lane & 15) * FPV + ((lane >> 4) << 4));

    prefetch(0, 0);          // commits group incl. Q
    CP_WAIT0();
    __syncthreads();

    for (int c = 0; c < 32; c++) {
        const int st = c & 1;
        if (c + 1 < 32) prefetch(c + 1, st ^ 1);   // issue at top, wait at bottom

        const uint32_t KHI = sb + KP_O + st * 36864;
        const uint32_t KLO = KHI + 18432;
        const uint32_t VHI = sb + VP_O + st * 45056;
        const uint32_t VLO = VHI + 22528;

        // ---- MMA1: S fragments (rows mrow..mrow+15, cols 0..127 of chunk)
        float acc1[16][4];
#pragma unroll
        for (int i = 0; i < 16; i++)
#pragma unroll
            for (int j = 0; j < 4; j++) acc1[i][j] = 0.f;

#pragma unroll
        for (int ks = 0; ks < 4; ks++) {
            uint32_t ah[4], al[4];
            LDSM4(ah, QHI + (uint32_t)(mrow * FPK + ks * 32) + lqk);
            LDSM4(al, QLO + (uint32_t)(mrow * FPK + ks * 32) + lqk);
#pragma unroll
            for (int nt2 = 0; nt2 < 8; nt2++) {
                uint32_t th[4], tl[4];
                LDSM4(th, KHI + (uint32_t)(nt2 * 16 * FPK + ks * 32) + lqk);
                LDSM4(tl, KLO + (uint32_t)(nt2 * 16 * FPK + ks * 32) + lqk);
                uint32_t b0h[2] = {th[0], th[2]}, b1h[2] = {th[1], th[3]};
                uint32_t b0l[2] = {tl[0], tl[2]}, b1l[2] = {tl[1], tl[3]};
                MMA16816(acc1[2*nt2],   ah, b0h);
                MMA16816(acc1[2*nt2],   ah, b0l);
                MMA16816(acc1[2*nt2],   al, b0h);
                MMA16816(acc1[2*nt2+1], ah, b1h);
                MMA16816(acc1[2*nt2+1], ah, b1l);
                MMA16816(acc1[2*nt2+1], al, b1h);
            }
        }

        // ---- exp (no max: |S| <~1.6) + column sum over n=128
#pragma unroll
        for (int nt = 0; nt < 16; nt++) {
            acc1[nt][0] = __expf(acc1[nt][0]);
            acc1[nt][1] = __expf(acc1[nt][1]);
            acc1[nt][2] = __expf(acc1[nt][2]);
            acc1[nt][3] = __expf(acc1[nt][3]);
            float s0 = acc1[nt][0] + acc1[nt][2];
            float s1 = acc1[nt][1] + acc1[nt][3];
            s0 += __shfl_xor_sync(0xffffffffu, s0, 4);
            s0 += __shfl_xor_sync(0xffffffffu, s0, 8);
            s0 += __shfl_xor_sync(0xffffffffu, s0, 16);
            s1 += __shfl_xor_sync(0xffffffffu, s1, 4);
            s1 += __shfl_xor_sync(0xffffffffu, s1, 8);
            s1 += __shfl_xor_sync(0xffffffffu, s1, 16);
            if (lane < 4) {
                cst[wid * 128 + nt * 8 + lane * 2]     = s0;
                cst[wid * 128 + nt * 8 + lane * 2 + 1] = s1;
            }
        }
        __syncthreads();
        if (tid < 128) {
            float s = 0.f;
#pragma unroll
            for (int w = 0; w < 8; w++) s += cst[w * 128 + tid];
            cst[1024 + tid] = 1.f / s;
        }
        __syncthreads();
#pragma unroll
        for (int nt = 0; nt < 16; nt++) {
            float2 iv = *reinterpret_cast<const float2*>(
                &cst[1024 + nt * 8 + (lane & 3) * 2]);
            acc1[nt][0] *= iv.x; acc1[nt][1] *= iv.y;
            acc1[nt][2] *= iv.x; acc1[nt][3] *= iv.y;
        }

        // ---- MMA2: acc2 += P @ [V | ones]
#pragma unroll
        for (int ks2 = 0; ks2 < 8; ks2++) {
            const float* p0 = acc1[2*ks2];
            const float* p1 = acc1[2*ks2+1];
            uint32_t pah[4], pal[4];
            pah[0] = pk2(p0[0], p0[1]); pal[0] = pk2lo(p0[0], p0[1], pah[0]);
            pah[1] = pk2(p0[2], p0[3]); pal[1] = pk2lo(p0[2], p0[3], pah[1]);
            pah[2] = pk2(p1[0], p1[1]); pal[2] = pk2lo(p1[0], p1[1], pah[2]);
            pah[3] = pk2(p1[2], p1[3]); pal[3] = pk2lo(p1[2], p1[3], pah[3]);
#pragma unroll
            for (int nt2 = 0; nt2 < 5; nt2++) {
                uint32_t th[4], tl[4];
                LDSM4T(th, VHI + (uint32_t)(ks2 * 16 * FPV + nt2 * 32) + lv);
                LDSM4T(tl, VLO + (uint32_t)(ks2 * 16 * FPV + nt2 * 32) + lv);
                uint32_t b0h[2] = {th[0], th[1]}, b0l[2] = {tl[0], tl[1]};
                MMA16816(acc2[2*nt2], pah, b0h);
                MMA16816(acc2[2*nt2], pah, b0l);
                MMA16816(acc2[2*nt2], pal, b0h);
                if (nt2 < 4) {
                    uint32_t b1h[2] = {th[2], th[3]}, b1l[2] = {tl[2], tl[3]};
                    MMA16816(acc2[2*nt2+1], pah, b1h);
                    MMA16816(acc2[2*nt2+1], pah, b1l);
                    MMA16816(acc2[2*nt2+1], pal, b1h);
                }
            }
        }

        if (c + 1 < 32) CP_WAIT0();   // next chunk landed during compute
        __syncthreads();
    }

    // ---- epilogue: divide by rowsum (ones column), write O planes
    float rs0 = __shfl_sync(0xffffffffu, acc2[8][0], lane & ~3);
    float rs2 = __shfl_sync(0xffffffffu, acc2[8][2], lane & ~3);
    float i0 = 1.f / rs0, i2 = 1.f / rs2;
    int r0 = mrow + (lane >> 2);
    long ob = (long)b * NN * DD + hh * DH;
#pragma unroll
    for (int nt = 0; nt < 8; nt++) {
        int cc = nt * 8 + (lane & 3) * 2;
        float a0 = acc2[nt][0] * i0, a1 = acc2[nt][1] * i0;
        float a2 = acc2[nt][2] * i2, a3 = acc2[nt][3] * i2;
        uint32_t h0 = pk2(a0, a1), l0 = pk2lo(a0, a1, h0);
        uint32_t h1 = pk2(a2, a3), l1 = pk2lo(a2, a3, h1);
        *reinterpret_cast<uint32_t*>(&Oh[ob + (long)r0 * DD + cc]) = h0;
        *reinterpret_cast<uint32_t*>(&Ol[ob + (long)r0 * DD + cc]) = l0;
        *reinterpret_cast<uint32_t*>(&Oh[ob + (long)(r0 + 8) * DD + cc]) = h1;
        *reinterpret_cast<uint32_t*>(&Ol[ob + (long)(r0 + 8) * DD + cc]) = l1;
    }
}

// ---------------- launch ----------------------------------------------------
extern "C" void kernel_launch(void* const* d_in, const int* in_sizes, int n_in,
                              void* d_out, int out_size)
{
    const float* q  = (const float*)d_in[0];
    const float* k  = (const float*)d_in[1];
    const float* v  = (const float*)d_in[2];
    const float* Wq = (const float*)d_in[3];
    const float* Wk = (const float*)d_in[4];
    const float* Wv = (const float*)d_in[5];
    const float* Wo = (const float*)d_in[6];
    float* out = (float*)d_out;

    bf16 *qh, *ql, *kh, *kl, *vh, *vl, *Wh, *Wl;
    bf16 *Qh, *Ql, *Kh, *Kl, *Vh, *Vl, *Oh, *Ol;
    cudaGetSymbolAddress((void**)&qh, g_qh); cudaGetSymbolAddress((void**)&ql, g_ql);
    cudaGetSymbolAddress((void**)&kh, g_kh); cudaGetSymbolAddress((void**)&kl, g_kl);
    cudaGetSymbolAddress((void**)&vh, g_vh); cudaGetSymbolAddress((void**)&vl, g_vl);
    cudaGetSymbolAddress((void**)&Wh, g_Wh); cudaGetSymbolAddress((void**)&Wl, g_Wl);
    cudaGetSymbolAddress((void**)&Qh, g_Qh); cudaGetSymbolAddress((void**)&Ql, g_Ql);
    cudaGetSymbolAddress((void**)&Kh, g_Kh); cudaGetSymbolAddress((void**)&Kl, g_Kl);
    cudaGetSymbolAddress((void**)&Vh, g_Vh); cudaGetSymbolAddress((void**)&Vl, g_Vl);
    cudaGetSymbolAddress((void**)&Oh, g_Oh); cudaGetSymbolAddress((void**)&Ol, g_Ol);

    cudaFuncSetAttribute((const void*)gemm_planes<true>,
                         cudaFuncAttributeMaxDynamicSharedMemorySize, PSMEM);
    cudaFuncSetAttribute((const void*)gemm_planes<false>,
                         cudaFuncAttributeMaxDynamicSharedMemorySize, PSMEM);
    cudaFuncSetAttribute((const void*)fused_attn,
                         cudaFuncAttributeMaxDynamicSharedMemorySize, FUSED_SMEM);

    const int WN4 = DD * DD / 4;
    const int QN4 = BB * NN * DD / 4;
    const int KN4 = BB * LL * DD / 4;

    split_kernel<<<QN4 / 256, 256>>>(q, qh, ql, QN4);
    split_kernel<<<KN4 / 256, 256>>>(k, kh, kl, KN4);
    split_kernel<<<KN4 / 256, 256>>>(v, vh, vl, KN4);
    split_kernel<<<WN4 / 256, 256>>>(Wq, Wh + 0*DD*DD, Wl + 0*DD*DD, WN4);
    split_kernel<<<WN4 / 256, 256>>>(Wk, Wh + 1*DD*DD, Wl + 1*DD*DD, WN4);
    split_kernel<<<WN4 / 256, 256>>>(Wv, Wh + 2*DD*DD, Wl + 2*DD*DD, WN4);
    split_kernel<<<WN4 / 256, 256>>>(Wo, Wh + 3*DD*DD, Wl + 3*DD*DD, WN4);

    const float SCALE = 0.03125f;  // D^-0.5, folded into Q projection

    gemm_planes<true><<<dim3(16, (BB*NN)/128), 256, PSMEM>>>(
        qh, ql, Wh + 0*DD*DD, Wl + 0*DD*DD, nullptr, Qh, Ql, DD, SCALE);
    gemm_planes<true><<<dim3(16, (BB*LL)/128), 256, PSMEM>>>(
        kh, kl, Wh + 1*DD*DD, Wl + 1*DD*DD, nullptr, Kh, Kl, DD, 1.f);
    gemm_planes<true><<<dim3(16, (BB*LL)/128), 256, PSMEM>>>(
        vh, vl, Wh + 2*DD*DD, Wl + 2*DD*DD, nullptr, Vh, Vl, DD, 1.f);

    fused_attn<<<BH, 256, FUSED_SMEM>>>(Qh, Ql, Kh, Kl, Vh, Vl, Oh, Ol);

    gemm_planes<false><<<dim3(16, (BB*NN)/128), 256, PSMEM>>>(
        Oh, Ol, Wh + 3*DD*DD, Wl + 3*DD*DD, out, nullptr, nullptr, DD, 1.f);
}

// round 7
// speedup vs baseline: 1.2474x; 1.0424x over previous
#include <cuda_runtime.h>
#include <cuda_bf16.h>
#include <cstdint>

// Problem constants
#define BB 8
#define NN 128
#define LL 4096
#define DD 1024
#define HH 16
#define DH 64
#define BH (BB*HH)          // 128

// ---------------- scratch (device globals) ----------------
__device__ float g_Qp[BB*NN*DD];            // 4 MB
__device__ float g_Kp[BB*LL*DD];            // 128 MB
__device__ float g_Vp[BB*LL*DD];            // 128 MB
__device__ float g_O [BB*NN*DD];            // 4 MB

// ---------------- helpers ----------------
__device__ __forceinline__ uint32_t smem_u32(const void* p) {
    uint32_t a;
    asm("{ .reg .u64 t; cvta.to.shared.u64 t, %1; cvt.u32.u64 %0, t; }"
        : "=r"(a) : "l"(p));
    return a;
}
__device__ __forceinline__ uint32_t pk2(float x, float y) {
    uint32_t r;
    asm("cvt.rn.bf16x2.f32 %0, %1, %2;" : "=r"(r) : "f"(y), "f"(x));
    return r;
}
__device__ __forceinline__ uint32_t pk2lo(float x, float y, uint32_t h) {
    float hx = __uint_as_float(h << 16);
    float hy = __uint_as_float(h & 0xFFFF0000u);
    uint32_t r;
    asm("cvt.rn.bf16x2.f32 %0, %1, %2;" : "=r"(r) : "f"(y - hy), "f"(x - hx));
    return r;
}
__device__ __forceinline__ void pack_hl(float4 v, uint64_t& H, uint64_t& L) {
    uint32_t h01 = pk2(v.x, v.y);
    uint32_t h23 = pk2(v.z, v.w);
    uint32_t l01 = pk2lo(v.x, v.y, h01);
    uint32_t l23 = pk2lo(v.z, v.w, h23);
    H = (uint64_t)h01 | ((uint64_t)h23 << 32);
    L = (uint64_t)l01 | ((uint64_t)l23 << 32);
}
__device__ __forceinline__ void sts64(uint32_t addr, uint64_t v) {
    asm volatile("st.shared.b64 [%0], %1;" :: "r"(addr), "l"(v) : "memory");
}
__device__ __forceinline__ void sts32(uint32_t addr, uint32_t v) {
    asm volatile("st.shared.b32 [%0], %1;" :: "r"(addr), "r"(v) : "memory");
}
__device__ __forceinline__ void cp16(uint32_t s, const void* g) {
    asm volatile("cp.async.cg.shared.global [%0], [%1], 16;" :: "r"(s), "l"(g));
}
#define CP_COMMIT() asm volatile("cp.async.commit_group;" ::: "memory")
#define CP_WAIT0()  asm volatile("cp.async.wait_group 0;" ::: "memory")

#define LDSM4(r, a) \
    asm volatile("ldmatrix.sync.aligned.m8n8.x4.shared.b16 {%0,%1,%2,%3}, [%4];" \
        : "=r"((r)[0]), "=r"((r)[1]), "=r"((r)[2]), "=r"((r)[3]) : "r"(a))
#define LDSM4T(r, a) \
    asm volatile("ldmatrix.sync.aligned.m8n8.x4.trans.shared.b16 {%0,%1,%2,%3}, [%4];" \
        : "=r"((r)[0]), "=r"((r)[1]), "=r"((r)[2]), "=r"((r)[3]) : "r"(a))

#define MMA16816(d, a, b) \
    asm volatile("mma.sync.aligned.m16n8k16.row.col.f32.bf16.bf16.f32 " \
        "{%0,%1,%2,%3}, {%4,%5,%6,%7}, {%8,%9}, {%0,%1,%2,%3};" \
        : "+f"((d)[0]), "+f"((d)[1]), "+f"((d)[2]), "+f"((d)[3]) \
        : "r"((a)[0]), "r"((a)[1]), "r"((a)[2]), "r"((a)[3]), \
          "r"((b)[0]), "r"((b)[1]))

// ---------------- bf16x3 NT GEMM: C = alpha * A @ B^T ------------------------
// Tile 128x128, BK = 32 fp32. 8 warps = 4(m) x 2(n), warp tile 32x64.
// SMEM rows: 144B pitch, [hi 64B | lo 64B | pad 16B]. lda=ldb=ldc=DD.
#define GPK 144
#define GT_SZ (128*GPK)              // 18432 (A or B tile per stage)
#define GSTAGE (2*GT_SZ)             // 36864
#define GSMEM (2*GSTAGE)             // 73728

__global__ void __launch_bounds__(256, 1)
gemm_mma(const float* __restrict__ A, const float* __restrict__ Bp,
         float* __restrict__ Cg, float alpha)
{
    extern __shared__ char smem[];
    const uint32_t sb = smem_u32(smem);

    const int tid  = threadIdx.x;
    const int wid  = tid >> 5, lane = tid & 31;
    const int wm   = wid & 3, wn = wid >> 2;     // 4(m) x 2(n)

    const int m0 = blockIdx.y * 128;
    const int n0 = blockIdx.x * 128;

    float acc[2][8][4];
#pragma unroll
    for (int i = 0; i < 2; i++)
#pragma unroll
        for (int j = 0; j < 8; j++)
#pragma unroll
            for (int q = 0; q < 4; q++) acc[i][j][q] = 0.f;

    const int NC = DD >> 5;          // 32 chunks
    float4 ra[4], rb[4];
    const int lrow = tid >> 3;       // 0..31
    const int lseg = tid & 7;        // float4 segment within 32-fp32 row

    auto ldg = [&](int c) {
        const int k0 = c << 5;
#pragma unroll
        for (int i = 0; i < 4; i++)
            ra[i] = *reinterpret_cast<const float4*>(
                &A[(long)(m0 + lrow + (i << 5)) * DD + k0 + (lseg << 2)]);
#pragma unroll
        for (int i = 0; i < 4; i++)
            rb[i] = *reinterpret_cast<const float4*>(
                &Bp[(long)(n0 + lrow + (i << 5)) * DD + k0 + (lseg << 2)]);
    };
    auto sts_stage = [&](int st) {
        const uint32_t abase = sb + st * GSTAGE;
        const uint32_t bbase = abase + GT_SZ;
#pragma unroll
        for (int i = 0; i < 4; i++) {
            uint64_t H, L; pack_hl(ra[i], H, L);
            uint32_t o = (uint32_t)((lrow + (i << 5)) * GPK + (lseg << 3));
            sts64(abase + o, H); sts64(abase + o + 64, L);
        }
#pragma unroll
        for (int i = 0; i < 4; i++) {
            uint64_t H, L; pack_hl(rb[i], H, L);
            uint32_t o = (uint32_t)((lrow + (i << 5)) * GPK + (lseg << 3));
            sts64(bbase + o, H); sts64(bbase + o + 64, L);
        }
    };

    const uint32_t lmo = (uint32_t)((lane & 15) * GPK + ((lane >> 4) << 4));

    auto compute = [&](int st) {
        const uint32_t abase = sb + st * GSTAGE;
        const uint32_t bbase = abase + GT_SZ;
#pragma unroll
        for (int ks = 0; ks < 2; ks++) {
            uint32_t ah[2][4], al[2][4];
#pragma unroll
            for (int mt = 0; mt < 2; mt++) {
                uint32_t ad = abase + (uint32_t)((wm * 32 + mt * 16) * GPK + ks * 32) + lmo;
                LDSM4(ah[mt], ad);
                LDSM4(al[mt], ad + 64);
            }
            uint32_t bhp[8][2], blp[8][2];
#pragma unroll
            for (int j = 0; j < 4; j++) {
                uint32_t bd = bbase + (uint32_t)((wn * 64 + j * 16) * GPK + ks * 32) + lmo;
                uint32_t t[4];
                LDSM4(t, bd);
                bhp[2*j][0] = t[0]; bhp[2*j][1] = t[2];
                bhp[2*j+1][0] = t[1]; bhp[2*j+1][1] = t[3];
                LDSM4(t, bd + 64);
                blp[2*j][0] = t[0]; blp[2*j][1] = t[2];
                blp[2*j+1][0] = t[1]; blp[2*j+1][1] = t[3];
            }
#pragma unroll
            for (int mt = 0; mt < 2; mt++)
#pragma unroll
                for (int nt = 0; nt < 8; nt++) {
                    MMA16816(acc[mt][nt], ah[mt], bhp[nt]);
                    MMA16816(acc[mt][nt], ah[mt], blp[nt]);
                    MMA16816(acc[mt][nt], al[mt], bhp[nt]);
                }
        }
    };

    ldg(0);
    sts_stage(0);
    __syncthreads();

    for (int c = 0; c < NC; c++) {
        if (c + 1 < NC) ldg(c + 1);
        compute(c & 1);
        if (c + 1 < NC) sts_stage((c + 1) & 1);
        __syncthreads();
    }

#pragma unroll
    for (int mt = 0; mt < 2; mt++) {
        int mr = m0 + wm * 32 + mt * 16 + (lane >> 2);
#pragma unroll
        for (int nt = 0; nt < 8; nt++) {
            int col = n0 + wn * 64 + nt * 8 + (lane & 3) * 2;
            float2 v0, v1;
            v0.x = acc[mt][nt][0] * alpha; v0.y = acc[mt][nt][1] * alpha;
            v1.x = acc[mt][nt][2] * alpha; v1.y = acc[mt][nt][3] * alpha;
            *reinterpret_cast<float2*>(&Cg[(long)mr * DD + col]) = v0;
            *reinterpret_cast<float2*>(&Cg[(long)(mr + 8) * DD + col]) = v1;
        }
    }
}

// ---------------- fused attention -------------------------------------------
// One CTA per (b,h). S = Q@K^T chunkwise; exact column softmax over n=128
// (no max subtraction: S ~ N(0, 0.25^2), |S|max ~ 1.5); P@[V|ones];
// epilogue divides by rowsum (ones column).
#define FPK 144            // Q/K plane pitch (64 bf16 + pad)
#define FPV 176            // V plane pitch (72 bf16 + pad)
#define QHI_O 0
#define QLO_O 18432
#define KHI_O 36864
#define KLO_O 55296
#define VHI_O 73728
#define VLO_O 96256
#define STK_O 118784
#define STV_O 151552
#define CST_O 184320
#define FUSED_SMEM (CST_O + 9*128*4)   // 188928

__global__ void __launch_bounds__(256, 1)
fused_attn(const float* __restrict__ Qp, const float* __restrict__ Kp,
           const float* __restrict__ Vp, float* __restrict__ O)
{
    extern __shared__ char smem[];
    const uint32_t sb = smem_u32(smem);
    float* cst = reinterpret_cast<float*>(smem + CST_O);

    const int tid = threadIdx.x, wid = tid >> 5, lane = tid & 31;
    const int bh = blockIdx.x, b = bh >> 4, h = bh & 15;
    const float* Qg = Qp + (long)b * NN * DD + h * DH;
    const float* Kg = Kp + (long)b * LL * DD + h * DH;
    const float* Vg = Vp + (long)b * LL * DD + h * DH;

    const uint32_t QHI = sb + QHI_O, QLO = sb + QLO_O;
    const uint32_t KHI = sb + KHI_O, KLO = sb + KLO_O;
    const uint32_t VHI = sb + VHI_O, VLO = sb + VLO_O;
    const uint32_t STK = sb + STK_O, STV = sb + STV_O;

    // init V ones columns (64..71) + zero pad (72..79), both planes
    for (int r = tid; r < 128; r += 256) {
        uint32_t ro = (uint32_t)r * FPV;
#pragma unroll
        for (int cb = 0; cb < 4; cb++) {
            sts32(VHI + ro + 128 + cb * 4, 0x3F803F80u);  // bf16 1.0 x2
            sts32(VLO + ro + 128 + cb * 4, 0u);
            sts32(VHI + ro + 144 + cb * 4, 0u);           // pad zeros
            sts32(VLO + ro + 144 + cb * 4, 0u);
        }
    }

    // load Q (scaled by D^-0.5) into bf16 hi/lo planes
    const float SCALE = 0.03125f;
#pragma unroll
    for (int i = 0; i < 8; i++) {
        int idx = tid + i * 256;
        int r = idx >> 4, s = idx & 15;
        float4 v = *reinterpret_cast<const float4*>(&Qg[(long)r * DD + s * 4]);
        v.x *= SCALE; v.y *= SCALE; v.z *= SCALE; v.w *= SCALE;
        uint64_t H, L; pack_hl(v, H, L);
        sts64(QHI + r * FPK + s * 8, H);
        sts64(QLO + r * FPK + s * 8, L);
    }

    auto cpasync_chunk = [&](int c) {
        long l0 = (long)c * 128;
#pragma unroll
        for (int i = 0; i < 8; i++) {
            int idx = tid + i * 256;
            int r = idx >> 4, s = idx & 15;
            cp16(STK + (uint32_t)(r * 256 + s * 16), &Kg[(l0 + r) * DD + s * 4]);
            cp16(STV + (uint32_t)(r * 256 + s * 16), &Vg[(l0 + r) * DD + s * 4]);
        }
        CP_COMMIT();
    };
    auto cvt_chunk = [&]() {
        const float4* stk = reinterpret_cast<const float4*>(smem + STK_O);
        const float4* stv = reinterpret_cast<const float4*>(smem + STV_O);
#pragma unroll
        for (int i = 0; i < 8; i++) {
            int idx = tid + i * 256;
            int r = idx >> 4, s = idx & 15;
            uint64_t H, L;
            pack_hl(stk[r * 16 + s], H, L);
            sts64(KHI + r * FPK + s * 8, H);
            sts64(KLO + r * FPK + s * 8, L);
            pack_hl(stv[r * 16 + s], H, L);
            sts64(VHI + r * FPV + s * 8, H);
            sts64(VLO + r * FPV + s * 8, L);
        }
    };

    float acc2[9][4];
#pragma unroll
    for (int i = 0; i < 9; i++)
#pragma unroll
        for (int j = 0; j < 4; j++) acc2[i][j] = 0.f;

    const int mrow = wid * 16;
    const uint32_t lqk = (uint32_t)((lane & 15) * FPK + ((lane >> 4) << 4));
    const uint32_t lv  = (uint32_t)((lane & 15) * FPV + ((lane >> 4) << 4));

    cpasync_chunk(0);
    CP_WAIT0();
    __syncthreads();
    cvt_chunk();
    __syncthreads();

    for (int c = 0; c < 32; c++) {
        if (c + 1 < 32) cpasync_chunk(c + 1);

        // ---- MMA1: S fragments acc1[nt 0..15][4], rows mrow..mrow+15
        float acc1[16][4];
#pragma unroll
        for (int i = 0; i < 16; i++)
#pragma unroll
            for (int j = 0; j < 4; j++) acc1[i][j] = 0.f;

#pragma unroll
        for (int ks = 0; ks < 4; ks++) {
            uint32_t ah[4], al[4];
            LDSM4(ah, QHI + (uint32_t)(mrow * FPK + ks * 32) + lqk);
            LDSM4(al, QLO + (uint32_t)(mrow * FPK + ks * 32) + lqk);
#pragma unroll
            for (int nt2 = 0; nt2 < 8; nt2++) {
                uint32_t th[4], tl[4];
                LDSM4(th, KHI + (uint32_t)(nt2 * 16 * FPK + ks * 32) + lqk);
                LDSM4(tl, KLO + (uint32_t)(nt2 * 16 * FPK + ks * 32) + lqk);
                uint32_t b0h[2] = {th[0], th[2]}, b1h[2] = {th[1], th[3]};
                uint32_t b0l[2] = {tl[0], tl[2]}, b1l[2] = {tl[1], tl[3]};
                MMA16816(acc1[2*nt2],   ah, b0h);
                MMA16816(acc1[2*nt2],   ah, b0l);
                MMA16816(acc1[2*nt2],   al, b0h);
                MMA16816(acc1[2*nt2+1], ah, b1h);
                MMA16816(acc1[2*nt2+1], ah, b1l);
                MMA16816(acc1[2*nt2+1], al, b1h);
            }
        }

        // ---- exp (no max subtraction) + column sum over n=128
#pragma unroll
        for (int nt = 0; nt < 16; nt++) {
            acc1[nt][0] = __expf(acc1[nt][0]);
            acc1[nt][1] = __expf(acc1[nt][1]);
            acc1[nt][2] = __expf(acc1[nt][2]);
            acc1[nt][3] = __expf(acc1[nt][3]);
            float s0 = acc1[nt][0] + acc1[nt][2];
            float s1 = acc1[nt][1] + acc1[nt][3];
            s0 += __shfl_xor_sync(0xffffffffu, s0, 4);
            s0 += __shfl_xor_sync(0xffffffffu, s0, 8);
            s0 += __shfl_xor_sync(0xffffffffu, s0, 16);
            s1 += __shfl_xor_sync(0xffffffffu, s1, 4);
            s1 += __shfl_xor_sync(0xffffffffu, s1, 8);
            s1 += __shfl_xor_sync(0xffffffffu, s1, 16);
            if (lane < 4) {
                cst[wid * 128 + nt * 8 + lane * 2]     = s0;
                cst[wid * 128 + nt * 8 + lane * 2 + 1] = s1;
            }
        }
        __syncthreads();
        if (tid < 128) {
            float s = 0.f;
#pragma unroll
            for (int w = 0; w < 8; w++) s += cst[w * 128 + tid];
            cst[1024 + tid] = 1.f / s;
        }
        __syncthreads();
#pragma unroll
        for (int nt = 0; nt < 16; nt++) {
            float2 iv = *reinterpret_cast<const float2*>(
                &cst[1024 + nt * 8 + (lane & 3) * 2]);
            acc1[nt][0] *= iv.x; acc1[nt][1] *= iv.y;
            acc1[nt][2] *= iv.x; acc1[nt][3] *= iv.y;
        }

        // ---- MMA2: acc2 += P @ [V | ones]  (A = acc1 fragments, registers)
#pragma unroll
        for (int ks2 = 0; ks2 < 8; ks2++) {
            const float* p0 = acc1[2*ks2];
            const float* p1 = acc1[2*ks2+1];
            uint32_t pah[4], pal[4];
            pah[0] = pk2(p0[0], p0[1]); pal[0] = pk2lo(p0[0], p0[1], pah[0]);
            pah[1] = pk2(p0[2], p0[3]); pal[1] = pk2lo(p0[2], p0[3], pah[1]);
            pah[2] = pk2(p1[0], p1[1]); pal[2] = pk2lo(p1[0], p1[1], pah[2]);
            pah[3] = pk2(p1[2], p1[3]); pal[3] = pk2lo(p1[2], p1[3], pah[3]);
#pragma unroll
            for (int nt2 = 0; nt2 < 5; nt2++) {
                uint32_t th[4], tl[4];
                LDSM4T(th, VHI + (uint32_t)(ks2 * 16 * FPV + nt2 * 32) + lv);
                LDSM4T(tl, VLO + (uint32_t)(ks2 * 16 * FPV + nt2 * 32) + lv);
                uint32_t b0h[2] = {th[0], th[1]}, b0l[2] = {tl[0], tl[1]};
                MMA16816(acc2[2*nt2], pah, b0h);
                MMA16816(acc2[2*nt2], pah, b0l);
                MMA16816(acc2[2*nt2], pal, b0h);
                if (nt2 < 4) {
                    uint32_t b1h[2] = {th[2], th[3]}, b1l[2] = {tl[2], tl[3]};
                    MMA16816(acc2[2*nt2+1], pah, b1h);
                    MMA16816(acc2[2*nt2+1], pah, b1l);
                    MMA16816(acc2[2*nt2+1], pal, b1h);
                }
            }
        }

        if (c + 1 < 32) CP_WAIT0();
        __syncthreads();             // all reads of K/V planes done; staging landed
        if (c + 1 < 32) {
            cvt_chunk();
            __syncthreads();
        }
    }

    // ---- epilogue: divide by rowsum (ones column = acc2[8][0]/[2]), store O
    float rs0 = __shfl_sync(0xffffffffu, acc2[8][0], lane & ~3);
    float rs2 = __shfl_sync(0xffffffffu, acc2[8][2], lane & ~3);
    float i0 = 1.f / rs0, i2 = 1.f / rs2;
    int r0 = mrow + (lane >> 2);
    float* Ob = O + (long)b * NN * DD + h * DH;
#pragma unroll
    for (int nt = 0; nt < 8; nt++) {
        int cc = nt * 8 + (lane & 3) * 2;
        float2 v0, v1;
        v0.x = acc2[nt][0] * i0; v0.y = acc2[nt][1] * i0;
        v1.x = acc2[nt][2] * i2; v1.y = acc2[nt][3] * i2;
        *reinterpret_cast<float2*>(&Ob[(long)r0 * DD + cc]) = v0;
        *reinterpret_cast<float2*>(&Ob[(long)(r0 + 8) * DD + cc]) = v1;
    }
}

// ---------------- launch ----------------------------------------------------
extern "C" void kernel_launch(void* const* d_in, const int* in_sizes, int n_in,
                              void* d_out, int out_size)
{
    const float* q  = (const float*)d_in[0];
    const float* k  = (const float*)d_in[1];
    const float* v  = (const float*)d_in[2];
    const float* Wq = (const float*)d_in[3];
    const float* Wk = (const float*)d_in[4];
    const float* Wv = (const float*)d_in[5];
    const float* Wo = (const float*)d_in[6];
    float* out = (float*)d_out;

    float *Qp, *Kp, *Vp, *O;
    cudaGetSymbolAddress((void**)&Qp, g_Qp);
    cudaGetSymbolAddress((void**)&Kp, g_Kp);
    cudaGetSymbolAddress((void**)&Vp, g_Vp);
    cudaGetSymbolAddress((void**)&O,  g_O);

    cudaFuncSetAttribute((const void*)gemm_mma,
                         cudaFuncAttributeMaxDynamicSharedMemorySize, GSMEM);
    cudaFuncSetAttribute((const void*)fused_attn,
                         cudaFuncAttributeMaxDynamicSharedMemorySize, FUSED_SMEM);

    // projections (128x128 tiles)
    gemm_mma<<<dim3(DD/128, (BB*NN)/128), 256, GSMEM>>>(q, Wq, Qp, 1.f);
    gemm_mma<<<dim3(DD/128, (BB*LL)/128), 256, GSMEM>>>(k, Wk, Kp, 1.f);
    gemm_mma<<<dim3(DD/128, (BB*LL)/128), 256, GSMEM>>>(v, Wv, Vp, 1.f);

    // fused: scores + inverted softmax + L1 renorm + AV
    fused_attn<<<BH, 256, FUSED_SMEM>>>(Qp, Kp, Vp, O);

    // output projection
    gemm_mma<<<dim3(DD/128, (BB*NN)/128), 256, GSMEM>>>(O, Wo, out, 1.f);
}

// round 9
// speedup vs baseline: 1.3387x; 1.0732x over previous
#include <cuda_runtime.h>
#include <cuda_bf16.h>
#include <cstdint>

// Problem constants
#define BB 8
#define NN 128
#define LL 4096
#define DD 1024
#define HH 16
#define DH 64
#define BH (BB*HH)          // 128

// ---------------- scratch (device globals) ----------------
__device__ float g_Qp[BB*NN*DD];            // 4 MB
__device__ float g_Kp[BB*LL*DD];            // 128 MB
__device__ float g_Vp[BB*LL*DD];            // 128 MB
__device__ float g_O [BB*NN*DD];            // 4 MB

// ---------------- helpers ----------------
__device__ __forceinline__ uint32_t smem_u32(const void* p) {
    uint32_t a;
    asm("{ .reg .u64 t; cvta.to.shared.u64 t, %1; cvt.u32.u64 %0, t; }"
        : "=r"(a) : "l"(p));
    return a;
}
__device__ __forceinline__ uint32_t pk2(float x, float y) {
    uint32_t r;
    asm("cvt.rn.bf16x2.f32 %0, %1, %2;" : "=r"(r) : "f"(y), "f"(x));
    return r;
}
__device__ __forceinline__ uint32_t pk2lo(float x, float y, uint32_t h) {
    float hx = __uint_as_float(h << 16);
    float hy = __uint_as_float(h & 0xFFFF0000u);
    uint32_t r;
    asm("cvt.rn.bf16x2.f32 %0, %1, %2;" : "=r"(r) : "f"(y - hy), "f"(x - hx));
    return r;
}
__device__ __forceinline__ void pack_hl(float4 v, uint64_t& H, uint64_t& L) {
    uint32_t h01 = pk2(v.x, v.y);
    uint32_t h23 = pk2(v.z, v.w);
    uint32_t l01 = pk2lo(v.x, v.y, h01);
    uint32_t l23 = pk2lo(v.z, v.w, h23);
    H = (uint64_t)h01 | ((uint64_t)h23 << 32);
    L = (uint64_t)l01 | ((uint64_t)l23 << 32);
}
__device__ __forceinline__ void sts64(uint32_t addr, uint64_t v) {
    asm volatile("st.shared.b64 [%0], %1;" :: "r"(addr), "l"(v) : "memory");
}
__device__ __forceinline__ void sts32(uint32_t addr, uint32_t v) {
    asm volatile("st.shared.b32 [%0], %1;" :: "r"(addr), "r"(v) : "memory");
}
__device__ __forceinline__ void cp16(uint32_t s, const void* g) {
    asm volatile("cp.async.cg.shared.global [%0], [%1], 16;" :: "r"(s), "l"(g));
}
#define CP_COMMIT() asm volatile("cp.async.commit_group;" ::: "memory")
#define CP_WAIT0()  asm volatile("cp.async.wait_group 0;" ::: "memory")

#define LDSM4(r, a) \
    asm volatile("ldmatrix.sync.aligned.m8n8.x4.shared.b16 {%0,%1,%2,%3}, [%4];" \
        : "=r"((r)[0]), "=r"((r)[1]), "=r"((r)[2]), "=r"((r)[3]) : "r"(a))
#define LDSM4T(r, a) \
    asm volatile("ldmatrix.sync.aligned.m8n8.x4.trans.shared.b16 {%0,%1,%2,%3}, [%4];" \
        : "=r"((r)[0]), "=r"((r)[1]), "=r"((r)[2]), "=r"((r)[3]) : "r"(a))

#define MMA16816(d, a, b) \
    asm volatile("mma.sync.aligned.m16n8k16.row.col.f32.bf16.bf16.f32 " \
        "{%0,%1,%2,%3}, {%4,%5,%6,%7}, {%8,%9}, {%0,%1,%2,%3};" \
        : "+f"((d)[0]), "+f"((d)[1]), "+f"((d)[2]), "+f"((d)[3]) \
        : "r"((a)[0]), "r"((a)[1]), "r"((a)[2]), "r"((a)[3]), \
          "r"((b)[0]), "r"((b)[1]))

// ---------------- bf16x3 NT GEMM: C = alpha * A @ B^T ------------------------
// Tile 128x64, BK = 32 fp32, 8 warps = 4(m) x 2(n), warp tile 32x32, occ 2.
// SMEM rows: 144B pitch, [hi 64B | lo 64B | pad].
__global__ void __launch_bounds__(256, 2)
gemm_mma(const float* __restrict__ A, const float* __restrict__ Bp,
         float* __restrict__ Cg, int K, int lda, int ldb, int ldc, float alpha)
{
    constexpr int ABYTES = 128 * 144;
    constexpr int BBYTES = 64 * 144;
    constexpr int STAGE  = ABYTES + BBYTES;

    extern __shared__ char smem[];
    const uint32_t sb = smem_u32(smem);

    const int tid  = threadIdx.x;
    const int wid  = tid >> 5, lane = tid & 31;
    const int wm   = wid & 3, wn = wid >> 2;          // 4 x 2

    const int m0 = blockIdx.y * 128;
    const int n0 = blockIdx.x * 64;

    float acc[2][4][4];
#pragma unroll
    for (int i = 0; i < 2; i++)
#pragma unroll
        for (int j = 0; j < 4; j++)
#pragma unroll
            for (int q = 0; q < 4; q++) acc[i][j][q] = 0.f;

    const int NC = K >> 5;
    float4 ra[4], rb[2];
    const int lrow = tid >> 3;
    const int lseg = tid & 7;

    auto ldg = [&](int c) {
        const int k0 = c << 5;
#pragma unroll
        for (int i = 0; i < 4; i++)
            ra[i] = *reinterpret_cast<const float4*>(
                &A[(long)(m0 + lrow + (i << 5)) * lda + k0 + (lseg << 2)]);
#pragma unroll
        for (int i = 0; i < 2; i++)
            rb[i] = *reinterpret_cast<const float4*>(
                &Bp[(long)(n0 + lrow + (i << 5)) * ldb + k0 + (lseg << 2)]);
    };
    auto sts_stage = [&](int st) {
        const uint32_t abase = sb + st * STAGE;
        const uint32_t bbase = abase + ABYTES;
#pragma unroll
        for (int i = 0; i < 4; i++) {
            uint64_t H, L; pack_hl(ra[i], H, L);
            uint32_t o = (uint32_t)((lrow + (i << 5)) * 144 + (lseg << 3));
            sts64(abase + o, H); sts64(abase + o + 64, L);
        }
#pragma unroll
        for (int i = 0; i < 2; i++) {
            uint64_t H, L; pack_hl(rb[i], H, L);
            uint32_t o = (uint32_t)((lrow + (i << 5)) * 144 + (lseg << 3));
            sts64(bbase + o, H); sts64(bbase + o + 64, L);
        }
    };
    auto compute = [&](int st) {
        const uint32_t abase = sb + st * STAGE;
        const uint32_t bbase = abase + ABYTES;
        const uint32_t lmo = (uint32_t)(((lane & 15) * 144) + ((lane >> 4) << 4));
#pragma unroll
        for (int ks = 0; ks < 2; ks++) {
            uint32_t ah[2][4], al[2][4];
#pragma unroll
            for (int mt = 0; mt < 2; mt++) {
                uint32_t ad = abase + (uint32_t)((wm * 32 + mt * 16) * 144 + ks * 32) + lmo;
                LDSM4(ah[mt], ad);
                LDSM4(al[mt], ad + 64);
            }
            uint32_t bhp[4][2], blp[4][2];
#pragma unroll
            for (int j = 0; j < 2; j++) {
                uint32_t bd = bbase + (uint32_t)((wn * 32 + j * 16) * 144 + ks * 32) + lmo;
                uint32_t t[4];
                LDSM4(t, bd);
                bhp[2*j][0] = t[0]; bhp[2*j][1] = t[2];
                bhp[2*j+1][0] = t[1]; bhp[2*j+1][1] = t[3];
                LDSM4(t, bd + 64);
                blp[2*j][0] = t[0]; blp[2*j][1] = t[2];
                blp[2*j+1][0] = t[1]; blp[2*j+1][1] = t[3];
            }
            // three independent sweeps: each accumulator revisited every 8 MMAs
#pragma unroll
            for (int mt = 0; mt < 2; mt++)
#pragma unroll
                for (int nt = 0; nt < 4; nt++)
                    MMA16816(acc[mt][nt], ah[mt], bhp[nt]);
#pragma unroll
            for (int mt = 0; mt < 2; mt++)
#pragma unroll
                for (int nt = 0; nt < 4; nt++)
                    MMA16816(acc[mt][nt], ah[mt], blp[nt]);
#pragma unroll
            for (int mt = 0; mt < 2; mt++)
#pragma unroll
                for (int nt = 0; nt < 4; nt++)
                    MMA16816(acc[mt][nt], al[mt], bhp[nt]);
        }
    };

    ldg(0);
    sts_stage(0);
    __syncthreads();

    for (int c = 0; c < NC; c++) {
        if (c + 1 < NC) ldg(c + 1);
        compute(c & 1);
        if (c + 1 < NC) sts_stage((c + 1) & 1);
        __syncthreads();
    }

#pragma unroll
    for (int mt = 0; mt < 2; mt++) {
        int mr = m0 + wm * 32 + mt * 16 + (lane >> 2);
#pragma unroll
        for (int nt = 0; nt < 4; nt++) {
            int col = n0 + wn * 32 + nt * 8 + (lane & 3) * 2;
            float2 v0, v1;
            v0.x = acc[mt][nt][0] * alpha; v0.y = acc[mt][nt][1] * alpha;
            v1.x = acc[mt][nt][2] * alpha; v1.y = acc[mt][nt][3] * alpha;
            *reinterpret_cast<float2*>(&Cg[(long)mr * ldc + col]) = v0;
            *reinterpret_cast<float2*>(&Cg[(long)(mr + 8) * ldc + col]) = v1;
        }
    }
}

// ---------------- fused attention (R7, proven 209us) -------------------------
// One CTA per (b,h). S = Q@K^T chunkwise; exact column softmax over n=128
// (no max subtraction: S ~ N(0, 0.25^2)); P@[V|ones]; divide by rowsum.
#define FPK 144
#define FPV 176
#define QHI_O 0
#define QLO_O 18432
#define KHI_O 36864
#define KLO_O 55296
#define VHI_O 73728
#define VLO_O 96256
#define STK_O 118784
#define STV_O 151552
#define CST_O 184320
#define FUSED_SMEM (CST_O + 9*128*4)   // 188928

__global__ void __launch_bounds__(256, 1)
fused_attn(const float* __restrict__ Qp, const float* __restrict__ Kp,
           const float* __restrict__ Vp, float* __restrict__ O)
{
    extern __shared__ char smem[];
    const uint32_t sb = smem_u32(smem);
    float* cst = reinterpret_cast<float*>(smem + CST_O);

    const int tid = threadIdx.x, wid = tid >> 5, lane = tid & 31;
    const int bh = blockIdx.x, b = bh >> 4, h = bh & 15;
    const float* Qg = Qp + (long)b * NN * DD + h * DH;
    const float* Kg = Kp + (long)b * LL * DD + h * DH;
    const float* Vg = Vp + (long)b * LL * DD + h * DH;

    const uint32_t QHI = sb + QHI_O, QLO = sb + QLO_O;
    const uint32_t KHI = sb + KHI_O, KLO = sb + KLO_O;
    const uint32_t VHI = sb + VHI_O, VLO = sb + VLO_O;
    const uint32_t STK = sb + STK_O, STV = sb + STV_O;

    for (int r = tid; r < 128; r += 256) {
        uint32_t ro = (uint32_t)r * FPV;
#pragma unroll
        for (int cb = 0; cb < 4; cb++) {
            sts32(VHI + ro + 128 + cb * 4, 0x3F803F80u);
            sts32(VLO + ro + 128 + cb * 4, 0u);
            sts32(VHI + ro + 144 + cb * 4, 0u);
            sts32(VLO + ro + 144 + cb * 4, 0u);
        }
    }

    const float SCALE = 0.03125f;
#pragma unroll
    for (int i = 0; i < 8; i++) {
        int idx = tid + i * 256;
        int r = idx >> 4, s = idx & 15;
        float4 v = *reinterpret_cast<const float4*>(&Qg[(long)r * DD + s * 4]);
        v.x *= SCALE; v.y *= SCALE; v.z *= SCALE; v.w *= SCALE;
        uint64_t H, L; pack_hl(v, H, L);
        sts64(QHI + r * FPK + s * 8, H);
        sts64(QLO + r * FPK + s * 8, L);
    }

    auto cpasync_chunk = [&](int c) {
        long l0 = (long)c * 128;
#pragma unroll
        for (int i = 0; i < 8; i++) {
            int idx = tid + i * 256;
            int r = idx >> 4, s = idx & 15;
            cp16(STK + (uint32_t)(r * 256 + s * 16), &Kg[(l0 + r) * DD + s * 4]);
            cp16(STV + (uint32_t)(r * 256 + s * 16), &Vg[(l0 + r) * DD + s * 4]);
        }
        CP_COMMIT();
    };
    auto cvt_chunk = [&]() {
        const float4* stk = reinterpret_cast<const float4*>(smem + STK_O);
        const float4* stv = reinterpret_cast<const float4*>(smem + STV_O);
#pragma unroll
        for (int i = 0; i < 8; i++) {
            int idx = tid + i * 256;
            int r = idx >> 4, s = idx & 15;
            uint64_t H, L;
            pack_hl(stk[r * 16 + s], H, L);
            sts64(KHI + r * FPK + s * 8, H);
            sts64(KLO + r * FPK + s * 8, L);
            pack_hl(stv[r * 16 + s], H, L);
            sts64(VHI + r * FPV + s * 8, H);
            sts64(VLO + r * FPV + s * 8, L);
        }
    };

    float acc2[9][4];
#pragma unroll
    for (int i = 0; i < 9; i++)
#pragma unroll
        for (int j = 0; j < 4; j++) acc2[i][j] = 0.f;

    const int mrow = wid * 16;
    const uint32_t lqk = (uint32_t)((lane & 15) * FPK + ((lane >> 4) << 4));
    const uint32_t lv  = (uint32_t)((lane & 15) * FPV + ((lane >> 4) << 4));

    cpasync_chunk(0);
    CP_WAIT0();
    __syncthreads();
    cvt_chunk();
    __syncthreads();

    for (int c = 0; c < 32; c++) {
        if (c + 1 < 32) cpasync_chunk(c + 1);

        float acc1[16][4];
#pragma unroll
        for (int i = 0; i < 16; i++)
#pragma unroll
            for (int j = 0; j < 4; j++) acc1[i][j] = 0.f;

#pragma unroll
        for (int ks = 0; ks < 4; ks++) {
            uint32_t ah[4], al[4];
            LDSM4(ah, QHI + (uint32_t)(mrow * FPK + ks * 32) + lqk);
            LDSM4(al, QLO + (uint32_t)(mrow * FPK + ks * 32) + lqk);
#pragma unroll
            for (int nt2 = 0; nt2 < 8; nt2++) {
                uint32_t th[4], tl[4];
                LDSM4(th, KHI + (uint32_t)(nt2 * 16 * FPK + ks * 32) + lqk);
                LDSM4(tl, KLO + (uint32_t)(nt2 * 16 * FPK + ks * 32) + lqk);
                uint32_t b0h[2] = {th[0], th[2]}, b1h[2] = {th[1], th[3]};
                uint32_t b0l[2] = {tl[0], tl[2]}, b1l[2] = {tl[1], tl[3]};
                MMA16816(acc1[2*nt2],   ah, b0h);
                MMA16816(acc1[2*nt2],   ah, b0l);
                MMA16816(acc1[2*nt2],   al, b0h);
                MMA16816(acc1[2*nt2+1], ah, b1h);
                MMA16816(acc1[2*nt2+1], ah, b1l);
                MMA16816(acc1[2*nt2+1], al, b1h);
            }
        }

#pragma unroll
        for (int nt = 0; nt < 16; nt++) {
            acc1[nt][0] = __expf(acc1[nt][0]);
            acc1[nt][1] = __expf(acc1[nt][1]);
            acc1[nt][2] = __expf(acc1[nt][2]);
            acc1[nt][3] = __expf(acc1[nt][3]);
            float s0 = acc1[nt][0] + acc1[nt][2];
            float s1 = acc1[nt][1] + acc1[nt][3];
            s0 += __shfl_xor_sync(0xffffffffu, s0, 4);
            s0 += __shfl_xor_sync(0xffffffffu, s0, 8);
            s0 += __shfl_xor_sync(0xffffffffu, s0, 16);
            s1 += __shfl_xor_sync(0xffffffffu, s1, 4);
            s1 += __shfl_xor_sync(0xffffffffu, s1, 8);
            s1 += __shfl_xor_sync(0xffffffffu, s1, 16);
            if (lane < 4) {
                cst[wid * 128 + nt * 8 + lane * 2]     = s0;
                cst[wid * 128 + nt * 8 + lane * 2 + 1] = s1;
            }
        }
        __syncthreads();
        if (tid < 128) {
            float s = 0.f;
#pragma unroll
            for (int w = 0; w < 8; w++) s += cst[w * 128 + tid];
            cst[1024 + tid] = 1.f / s;
        }
        __syncthreads();
#pragma unroll
        for (int nt = 0; nt < 16; nt++) {
            float2 iv = *reinterpret_cast<const float2*>(
                &cst[1024 + nt * 8 + (lane & 3) * 2]);
            acc1[nt][0] *= iv.x; acc1[nt][1] *= iv.y;
            acc1[nt][2] *= iv.x; acc1[nt][3] *= iv.y;
        }

#pragma unroll
        for (int ks2 = 0; ks2 < 8; ks2++) {
            const float* p0 = acc1[2*ks2];
            const float* p1 = acc1[2*ks2+1];
            uint32_t pah[4], pal[4];
            pah[0] = pk2(p0[0], p0[1]); pal[0] = pk2lo(p0[0], p0[1], pah[0]);
            pah[1] = pk2(p0[2], p0[3]); pal[1] = pk2lo(p0[2], p0[3], pah[1]);
            pah[2] = pk2(p1[0], p1[1]); pal[2] = pk2lo(p1[0], p1[1], pah[2]);
            pah[3] = pk2(p1[2], p1[3]); pal[3] = pk2lo(p1[2], p1[3], pah[3]);
#pragma unroll
            for (int nt2 = 0; nt2 < 5; nt2++) {
                uint32_t th[4], tl[4];
                LDSM4T(th, VHI + (uint32_t)(ks2 * 16 * FPV + nt2 * 32) + lv);
                LDSM4T(tl, VLO + (uint32_t)(ks2 * 16 * FPV + nt2 * 32) + lv);
                uint32_t b0h[2] = {th[0], th[1]}, b0l[2] = {tl[0], tl[1]};
                MMA16816(acc2[2*nt2], pah, b0h);
                MMA16816(acc2[2*nt2], pah, b0l);
                MMA16816(acc2[2*nt2], pal, b0h);
                if (nt2 < 4) {
                    uint32_t b1h[2] = {th[2], th[3]}, b1l[2] = {tl[2], tl[3]};
                    MMA16816(acc2[2*nt2+1], pah, b1h);
                    MMA16816(acc2[2*nt2+1], pah, b1l);
                    MMA16816(acc2[2*nt2+1], pal, b1h);
                }
            }
        }

        if (c + 1 < 32) CP_WAIT0();
        __syncthreads();
        if (c + 1 < 32) {
            cvt_chunk();
            __syncthreads();
        }
    }

    float rs0 = __shfl_sync(0xffffffffu, acc2[8][0], lane & ~3);
    float rs2 = __shfl_sync(0xffffffffu, acc2[8][2], lane & ~3);
    float i0 = 1.f / rs0, i2 = 1.f / rs2;
    int r0 = mrow + (lane >> 2);
    float* Ob = O + (long)b * NN * DD + h * DH;
#pragma unroll
    for (int nt = 0; nt < 8; nt++) {
        int cc = nt * 8 + (lane & 3) * 2;
        float2 v0, v1;
        v0.x = acc2[nt][0] * i0; v0.y = acc2[nt][1] * i0;
        v1.x = acc2[nt][2] * i2; v1.y = acc2[nt][3] * i2;
        *reinterpret_cast<float2*>(&Ob[(long)r0 * DD + cc]) = v0;
        *reinterpret_cast<float2*>(&Ob[(long)(r0 + 8) * DD + cc]) = v1;
    }
}

// ---------------- launch ----------------------------------------------------
extern "C" void kernel_launch(void* const* d_in, const int* in_sizes, int n_in,
                              void* d_out, int out_size)
{
    const float* q  = (const float*)d_in[0];
    const float* k  = (const float*)d_in[1];
    const float* v  = (const float*)d_in[2];
    const float* Wq = (const float*)d_in[3];
    const float* Wk = (const float*)d_in[4];
    const float* Wv = (const float*)d_in[5];
    const float* Wo = (const float*)d_in[6];
    float* out = (float*)d_out;

    float *Qp, *Kp, *Vp, *O;
    cudaGetSymbolAddress((void**)&Qp, g_Qp);
    cudaGetSymbolAddress((void**)&Kp, g_Kp);
    cudaGetSymbolAddress((void**)&Vp, g_Vp);
    cudaGetSymbolAddress((void**)&O,  g_O);

    const int SZG = 2 * (128 * 144 + 64 * 144);   // 55296
    cudaFuncSetAttribute((const void*)gemm_mma,
                         cudaFuncAttributeMaxDynamicSharedMemorySize, SZG);
    cudaFuncSetAttribute((const void*)fused_attn,
                         cudaFuncAttributeMaxDynamicSharedMemorySize, FUSED_SMEM);

    // projections (128x64 tiles, occ 2)
    gemm_mma<<<dim3(DD/64, (BB*NN)/128), 256, SZG>>>(
        q, Wq, Qp, DD, DD, DD, DD, 1.f);
    gemm_mma<<<dim3(DD/64, (BB*LL)/128), 256, SZG>>>(
        k, Wk, Kp, DD, DD, DD, DD, 1.f);
    gemm_mma<<<dim3(DD/64, (BB*LL)/128), 256, SZG>>>(
        v, Wv, Vp, DD, DD, DD, DD, 1.f);

    // fused: scores + inverted softmax + L1 renorm + AV
    fused_attn<<<BH, 256, FUSED_SMEM>>>(Qp, Kp, Vp, O);

    // output projection
    gemm_mma<<<dim3(DD/64, (BB*NN)/128), 256, SZG>>>(
        O, Wo, out, DD, DD, DD, DD, 1.f);
}

// round 10
// speedup vs baseline: 1.6662x; 1.2446x over previous
#include <cuda_runtime.h>
#include <cuda_bf16.h>
#include <cstdint>

// Problem constants
#define BB 8
#define NN 128
#define LL 4096
#define DD 1024
#define HH 16
#define DH 64
#define BH (BB*HH)          // 128

// ---------------- scratch (device globals) ----------------
__device__ float g_Qp[BB*NN*DD];            // 4 MB
__device__ float g_Kp[BB*LL*DD];            // 128 MB
__device__ float g_Vp[BB*LL*DD];            // 128 MB
__device__ float g_O [BB*NN*DD];            // 4 MB

// ---------------- helpers ----------------
__device__ __forceinline__ uint32_t smem_u32(const void* p) {
    uint32_t a;
    asm("{ .reg .u64 t; cvta.to.shared.u64 t, %1; cvt.u32.u64 %0, t; }"
        : "=r"(a) : "l"(p));
    return a;
}
__device__ __forceinline__ uint32_t pk2(float x, float y) {
    uint32_t r;
    asm("cvt.rn.bf16x2.f32 %0, %1, %2;" : "=r"(r) : "f"(y), "f"(x));
    return r;
}
__device__ __forceinline__ uint32_t pk2lo(float x, float y, uint32_t h) {
    float hx = __uint_as_float(h << 16);
    float hy = __uint_as_float(h & 0xFFFF0000u);
    uint32_t r;
    asm("cvt.rn.bf16x2.f32 %0, %1, %2;" : "=r"(r) : "f"(y - hy), "f"(x - hx));
    return r;
}
__device__ __forceinline__ void pack_hl(float4 v, uint64_t& H, uint64_t& L) {
    uint32_t h01 = pk2(v.x, v.y);
    uint32_t h23 = pk2(v.z, v.w);
    uint32_t l01 = pk2lo(v.x, v.y, h01);
    uint32_t l23 = pk2lo(v.z, v.w, h23);
    H = (uint64_t)h01 | ((uint64_t)h23 << 32);
    L = (uint64_t)l01 | ((uint64_t)l23 << 32);
}
__device__ __forceinline__ uint64_t pack_h(float4 v) {
    uint32_t h01 = pk2(v.x, v.y);
    uint32_t h23 = pk2(v.z, v.w);
    return (uint64_t)h01 | ((uint64_t)h23 << 32);
}
__device__ __forceinline__ void sts64(uint32_t addr, uint64_t v) {
    asm volatile("st.shared.b64 [%0], %1;" :: "r"(addr), "l"(v) : "memory");
}
__device__ __forceinline__ void sts32(uint32_t addr, uint32_t v) {
    asm volatile("st.shared.b32 [%0], %1;" :: "r"(addr), "r"(v) : "memory");
}
__device__ __forceinline__ void cp16(uint32_t s, const void* g) {
    asm volatile("cp.async.cg.shared.global [%0], [%1], 16;" :: "r"(s), "l"(g));
}
#define CP_COMMIT() asm volatile("cp.async.commit_group;" ::: "memory")
#define CP_WAIT0()  asm volatile("cp.async.wait_group 0;" ::: "memory")

#define LDSM4(r, a) \
    asm volatile("ldmatrix.sync.aligned.m8n8.x4.shared.b16 {%0,%1,%2,%3}, [%4];" \
        : "=r"((r)[0]), "=r"((r)[1]), "=r"((r)[2]), "=r"((r)[3]) : "r"(a))
#define LDSM4T(r, a) \
    asm volatile("ldmatrix.sync.aligned.m8n8.x4.trans.shared.b16 {%0,%1,%2,%3}, [%4];" \
        : "=r"((r)[0]), "=r"((r)[1]), "=r"((r)[2]), "=r"((r)[3]) : "r"(a))

#define MMA16816(d, a, b) \
    asm volatile("mma.sync.aligned.m16n8k16.row.col.f32.bf16.bf16.f32 " \
        "{%0,%1,%2,%3}, {%4,%5,%6,%7}, {%8,%9}, {%0,%1,%2,%3};" \
        : "+f"((d)[0]), "+f"((d)[1]), "+f"((d)[2]), "+f"((d)[3]) \
        : "r"((a)[0]), "r"((a)[1]), "r"((a)[2]), "r"((a)[3]), \
          "r"((b)[0]), "r"((b)[1]))

// ---------------- bf16 NT GEMM: C = alpha * A @ B^T --------------------------
// Tile 128x64, BK = 32 fp32, 8 warps = 4(m) x 2(n), warp tile 32x32, occ 2.
// SMEM rows: 144B pitch, [hi 64B | lo 64B | pad].
// NPASS=3: bf16x3 split (hi*hi + hi*lo + lo*hi), rel err ~2e-6.
// NPASS=1: plain bf16 (hi*hi only), rel err ~8e-4 — S-path only.
template<int NPASS>
__global__ void __launch_bounds__(256, 2)
gemm_mma(const float* __restrict__ A, const float* __restrict__ Bp,
         float* __restrict__ Cg, int K, int lda, int ldb, int ldc, float alpha)
{
    constexpr int ABYTES = 128 * 144;
    constexpr int BBYTES = 64 * 144;
    constexpr int STAGE  = ABYTES + BBYTES;

    extern __shared__ char smem[];
    const uint32_t sb = smem_u32(smem);

    const int tid  = threadIdx.x;
    const int wid  = tid >> 5, lane = tid & 31;
    const int wm   = wid & 3, wn = wid >> 2;          // 4 x 2

    const int m0 = blockIdx.y * 128;
    const int n0 = blockIdx.x * 64;

    float acc[2][4][4];
#pragma unroll
    for (int i = 0; i < 2; i++)
#pragma unroll
        for (int j = 0; j < 4; j++)
#pragma unroll
            for (int q = 0; q < 4; q++) acc[i][j][q] = 0.f;

    const int NC = K >> 5;
    float4 ra[4], rb[2];
    const int lrow = tid >> 3;
    const int lseg = tid & 7;

    auto ldg = [&](int c) {
        const int k0 = c << 5;
#pragma unroll
        for (int i = 0; i < 4; i++)
            ra[i] = *reinterpret_cast<const float4*>(
                &A[(long)(m0 + lrow + (i << 5)) * lda + k0 + (lseg << 2)]);
#pragma unroll
        for (int i = 0; i < 2; i++)
            rb[i] = *reinterpret_cast<const float4*>(
                &Bp[(long)(n0 + lrow + (i << 5)) * ldb + k0 + (lseg << 2)]);
    };
    auto sts_stage = [&](int st) {
        const uint32_t abase = sb + st * STAGE;
        const uint32_t bbase = abase + ABYTES;
#pragma unroll
        for (int i = 0; i < 4; i++) {
            uint32_t o = (uint32_t)((lrow + (i << 5)) * 144 + (lseg << 3));
            if (NPASS == 3) {
                uint64_t H, L; pack_hl(ra[i], H, L);
                sts64(abase + o, H); sts64(abase + o + 64, L);
            } else {
                sts64(abase + o, pack_h(ra[i]));
            }
        }
#pragma unroll
        for (int i = 0; i < 2; i++) {
            uint32_t o = (uint32_t)((lrow + (i << 5)) * 144 + (lseg << 3));
            if (NPASS == 3) {
                uint64_t H, L; pack_hl(rb[i], H, L);
                sts64(bbase + o, H); sts64(bbase + o + 64, L);
            } else {
                sts64(bbase + o, pack_h(rb[i]));
            }
        }
    };
    auto compute = [&](int st) {
        const uint32_t abase = sb + st * STAGE;
        const uint32_t bbase = abase + ABYTES;
        const uint32_t lmo = (uint32_t)(((lane & 15) * 144) + ((lane >> 4) << 4));
#pragma unroll
        for (int ks = 0; ks < 2; ks++) {
            uint32_t ah[2][4], al[2][4];
#pragma unroll
            for (int mt = 0; mt < 2; mt++) {
                uint32_t ad = abase + (uint32_t)((wm * 32 + mt * 16) * 144 + ks * 32) + lmo;
                LDSM4(ah[mt], ad);
                if (NPASS == 3) LDSM4(al[mt], ad + 64);
            }
            uint32_t bhp[4][2], blp[4][2];
#pragma unroll
            for (int j = 0; j < 2; j++) {
                uint32_t bd = bbase + (uint32_t)((wn * 32 + j * 16) * 144 + ks * 32) + lmo;
                uint32_t t[4];
                LDSM4(t, bd);
                bhp[2*j][0] = t[0]; bhp[2*j][1] = t[2];
                bhp[2*j+1][0] = t[1]; bhp[2*j+1][1] = t[3];
                if (NPASS == 3) {
                    LDSM4(t, bd + 64);
                    blp[2*j][0] = t[0]; blp[2*j][1] = t[2];
                    blp[2*j+1][0] = t[1]; blp[2*j+1][1] = t[3];
                }
            }
            // independent sweeps: each accumulator revisited every 8 MMAs
#pragma unroll
            for (int mt = 0; mt < 2; mt++)
#pragma unroll
                for (int nt = 0; nt < 4; nt++)
                    MMA16816(acc[mt][nt], ah[mt], bhp[nt]);
            if (NPASS == 3) {
#pragma unroll
                for (int mt = 0; mt < 2; mt++)
#pragma unroll
                    for (int nt = 0; nt < 4; nt++)
                        MMA16816(acc[mt][nt], ah[mt], blp[nt]);
#pragma unroll
                for (int mt = 0; mt < 2; mt++)
#pragma unroll
                    for (int nt = 0; nt < 4; nt++)
                        MMA16816(acc[mt][nt], al[mt], bhp[nt]);
            }
        }
    };

    ldg(0);
    sts_stage(0);
    __syncthreads();

    for (int c = 0; c < NC; c++) {
        if (c + 1 < NC) ldg(c + 1);
        compute(c & 1);
        if (c + 1 < NC) sts_stage((c + 1) & 1);
        __syncthreads();
    }

#pragma unroll
    for (int mt = 0; mt < 2; mt++) {
        int mr = m0 + wm * 32 + mt * 16 + (lane >> 2);
#pragma unroll
        for (int nt = 0; nt < 4; nt++) {
            int col = n0 + wn * 32 + nt * 8 + (lane & 3) * 2;
            float2 v0, v1;
            v0.x = acc[mt][nt][0] * alpha; v0.y = acc[mt][nt][1] * alpha;
            v1.x = acc[mt][nt][2] * alpha; v1.y = acc[mt][nt][3] * alpha;
            *reinterpret_cast<float2*>(&Cg[(long)mr * ldc + col]) = v0;
            *reinterpret_cast<float2*>(&Cg[(long)(mr + 8) * ldc + col]) = v1;
        }
    }
}

// ---------------- fused attention --------------------------------------------
// One CTA per (b,h). S = Q@K^T chunkwise in PLAIN bf16 (S-path tolerance);
// exact column softmax over n=128 (no max subtraction); P@[V|ones] in bf16x3;
// epilogue divides by rowsum (ones column).
#define FPK 144
#define FPV 176
#define QHI_O 0
#define KHI_O 36864
#define VHI_O 73728
#define VLO_O 96256
#define STK_O 118784
#define STV_O 151552
#define CST_O 184320
#define FUSED_SMEM (CST_O + 9*128*4)   // 188928

__global__ void __launch_bounds__(256, 1)
fused_attn(const float* __restrict__ Qp, const float* __restrict__ Kp,
           const float* __restrict__ Vp, float* __restrict__ O)
{
    extern __shared__ char smem[];
    const uint32_t sb = smem_u32(smem);
    float* cst = reinterpret_cast<float*>(smem + CST_O);

    const int tid = threadIdx.x, wid = tid >> 5, lane = tid & 31;
    const int bh = blockIdx.x, b = bh >> 4, h = bh & 15;
    const float* Qg = Qp + (long)b * NN * DD + h * DH;
    const float* Kg = Kp + (long)b * LL * DD + h * DH;
    const float* Vg = Vp + (long)b * LL * DD + h * DH;

    const uint32_t QHI = sb + QHI_O;
    const uint32_t KHI = sb + KHI_O;
    const uint32_t VHI = sb + VHI_O, VLO = sb + VLO_O;
    const uint32_t STK = sb + STK_O, STV = sb + STV_O;

    // init V ones columns (64..71) + zero pad (72..79), both planes
    for (int r = tid; r < 128; r += 256) {
        uint32_t ro = (uint32_t)r * FPV;
#pragma unroll
        for (int cb = 0; cb < 4; cb++) {
            sts32(VHI + ro + 128 + cb * 4, 0x3F803F80u);
            sts32(VLO + ro + 128 + cb * 4, 0u);
            sts32(VHI + ro + 144 + cb * 4, 0u);
            sts32(VLO + ro + 144 + cb * 4, 0u);
        }
    }

    // load Q (scaled by D^-0.5) into single bf16 plane
    const float SCALE = 0.03125f;
#pragma unroll
    for (int i = 0; i < 8; i++) {
        int idx = tid + i * 256;
        int r = idx >> 4, s = idx & 15;
        float4 v = *reinterpret_cast<const float4*>(&Qg[(long)r * DD + s * 4]);
        v.x *= SCALE; v.y *= SCALE; v.z *= SCALE; v.w *= SCALE;
        sts64(QHI + r * FPK + s * 8, pack_h(v));
    }

    auto cpasync_chunk = [&](int c) {
        long l0 = (long)c * 128;
#pragma unroll
        for (int i = 0; i < 8; i++) {
            int idx = tid + i * 256;
            int r = idx >> 4, s = idx & 15;
            cp16(STK + (uint32_t)(r * 256 + s * 16), &Kg[(l0 + r) * DD + s * 4]);
            cp16(STV + (uint32_t)(r * 256 + s * 16), &Vg[(l0 + r) * DD + s * 4]);
        }
        CP_COMMIT();
    };
    auto cvt_chunk = [&]() {
        const float4* stk = reinterpret_cast<const float4*>(smem + STK_O);
        const float4* stv = reinterpret_cast<const float4*>(smem + STV_O);
#pragma unroll
        for (int i = 0; i < 8; i++) {
            int idx = tid + i * 256;
            int r = idx >> 4, s = idx & 15;
            sts64(KHI + r * FPK + s * 8, pack_h(stk[r * 16 + s]));
            uint64_t H, L;
            pack_hl(stv[r * 16 + s], H, L);
            sts64(VHI + r * FPV + s * 8, H);
            sts64(VLO + r * FPV + s * 8, L);
        }
    };

    float acc2[9][4];
#pragma unroll
    for (int i = 0; i < 9; i++)
#pragma unroll
        for (int j = 0; j < 4; j++) acc2[i][j] = 0.f;

    const int mrow = wid * 16;
    const uint32_t lqk = (uint32_t)((lane & 15) * FPK + ((lane >> 4) << 4));
    const uint32_t lv  = (uint32_t)((lane & 15) * FPV + ((lane >> 4) << 4));

    cpasync_chunk(0);
    CP_WAIT0();
    __syncthreads();
    cvt_chunk();
    __syncthreads();

    for (int c = 0; c < 32; c++) {
        if (c + 1 < 32) cpasync_chunk(c + 1);

        // ---- MMA1: S fragments, plain bf16 Q,K (S-path error tolerance)
        float acc1[16][4];
#pragma unroll
        for (int i = 0; i < 16; i++)
#pragma unroll
            for (int j = 0; j < 4; j++) acc1[i][j] = 0.f;

#pragma unroll
        for (int ks = 0; ks < 4; ks++) {
            uint32_t ah[4];
            LDSM4(ah, QHI + (uint32_t)(mrow * FPK + ks * 32) + lqk);
#pragma unroll
            for (int nt2 = 0; nt2 < 8; nt2++) {
                uint32_t th[4];
                LDSM4(th, KHI + (uint32_t)(nt2 * 16 * FPK + ks * 32) + lqk);
                uint32_t b0h[2] = {th[0], th[2]}, b1h[2] = {th[1], th[3]};
                MMA16816(acc1[2*nt2],   ah, b0h);
                MMA16816(acc1[2*nt2+1], ah, b1h);
            }
        }

        // ---- exp (no max subtraction) + column sum over n=128
#pragma unroll
        for (int nt = 0; nt < 16; nt++) {
            acc1[nt][0] = __expf(acc1[nt][0]);
            acc1[nt][1] = __expf(acc1[nt][1]);
            acc1[nt][2] = __expf(acc1[nt][2]);
            acc1[nt][3] = __expf(acc1[nt][3]);
            float s0 = acc1[nt][0] + acc1[nt][2];
            float s1 = acc1[nt][1] + acc1[nt][3];
            s0 += __shfl_xor_sync(0xffffffffu, s0, 4);
            s0 += __shfl_xor_sync(0xffffffffu, s0, 8);
            s0 += __shfl_xor_sync(0xffffffffu, s0, 16);
            s1 += __shfl_xor_sync(0xffffffffu, s1, 4);
            s1 += __shfl_xor_sync(0xffffffffu, s1, 8);
            s1 += __shfl_xor_sync(0xffffffffu, s1, 16);
            if (lane < 4) {
                cst[wid * 128 + nt * 8 + lane * 2]     = s0;
                cst[wid * 128 + nt * 8 + lane * 2 + 1] = s1;
            }
        }
        __syncthreads();
        if (tid < 128) {
            float s = 0.f;
#pragma unroll
            for (int w = 0; w < 8; w++) s += cst[w * 128 + tid];
            cst[1024 + tid] = 1.f / s;
        }
        __syncthreads();
#pragma unroll
        for (int nt = 0; nt < 16; nt++) {
            float2 iv = *reinterpret_cast<const float2*>(
                &cst[1024 + nt * 8 + (lane & 3) * 2]);
            acc1[nt][0] *= iv.x; acc1[nt][1] *= iv.y;
            acc1[nt][2] *= iv.x; acc1[nt][3] *= iv.y;
        }

        // ---- MMA2: acc2 += P @ [V | ones]  (full bf16x3 precision)
#pragma unroll
        for (int ks2 = 0; ks2 < 8; ks2++) {
            const float* p0 = acc1[2*ks2];
            const float* p1 = acc1[2*ks2+1];
            uint32_t pah[4], pal[4];
            pah[0] = pk2(p0[0], p0[1]); pal[0] = pk2lo(p0[0], p0[1], pah[0]);
            pah[1] = pk2(p0[2], p0[3]); pal[1] = pk2lo(p0[2], p0[3], pah[1]);
            pah[2] = pk2(p1[0], p1[1]); pal[2] = pk2lo(p1[0], p1[1], pah[2]);
            pah[3] = pk2(p1[2], p1[3]); pal[3] = pk2lo(p1[2], p1[3], pah[3]);
#pragma unroll
            for (int nt2 = 0; nt2 < 5; nt2++) {
                uint32_t th[4], tl[4];
                LDSM4T(th, VHI + (uint32_t)(ks2 * 16 * FPV + nt2 * 32) + lv);
                LDSM4T(tl, VLO + (uint32_t)(ks2 * 16 * FPV + nt2 * 32) + lv);
                uint32_t b0h[2] = {th[0], th[1]}, b0l[2] = {tl[0], tl[1]};
                MMA16816(acc2[2*nt2], pah, b0h);
                MMA16816(acc2[2*nt2], pah, b0l);
                MMA16816(acc2[2*nt2], pal, b0h);
                if (nt2 < 4) {
                    uint32_t b1h[2] = {th[2], th[3]}, b1l[2] = {tl[2], tl[3]};
                    MMA16816(acc2[2*nt2+1], pah, b1h);
                    MMA16816(acc2[2*nt2+1], pah, b1l);
                    MMA16816(acc2[2*nt2+1], pal, b1h);
                }
            }
        }

        if (c + 1 < 32) CP_WAIT0();
        __syncthreads();
        if (c + 1 < 32) {
            cvt_chunk();
            __syncthreads();
        }
    }

    // ---- epilogue: divide by rowsum (ones column), store O
    float rs0 = __shfl_sync(0xffffffffu, acc2[8][0], lane & ~3);
    float rs2 = __shfl_sync(0xffffffffu, acc2[8][2], lane & ~3);
    float i0 = 1.f / rs0, i2 = 1.f / rs2;
    int r0 = mrow + (lane >> 2);
    float* Ob = O + (long)b * NN * DD + h * DH;
#pragma unroll
    for (int nt = 0; nt < 8; nt++) {
        int cc = nt * 8 + (lane & 3) * 2;
        float2 v0, v1;
        v0.x = acc2[nt][0] * i0; v0.y = acc2[nt][1] * i0;
        v1.x = acc2[nt][2] * i2; v1.y = acc2[nt][3] * i2;
        *reinterpret_cast<float2*>(&Ob[(long)r0 * DD + cc]) = v0;
        *reinterpret_cast<float2*>(&Ob[(long)(r0 + 8) * DD + cc]) = v1;
    }
}

// ---------------- launch ----------------------------------------------------
extern "C" void kernel_launch(void* const* d_in, const int* in_sizes, int n_in,
                              void* d_out, int out_size)
{
    const float* q  = (const float*)d_in[0];
    const float* k  = (const float*)d_in[1];
    const float* v  = (const float*)d_in[2];
    const float* Wq = (const float*)d_in[3];
    const float* Wk = (const float*)d_in[4];
    const float* Wv = (const float*)d_in[5];
    const float* Wo = (const float*)d_in[6];
    float* out = (float*)d_out;

    float *Qp, *Kp, *Vp, *O;
    cudaGetSymbolAddress((void**)&Qp, g_Qp);
    cudaGetSymbolAddress((void**)&Kp, g_Kp);
    cudaGetSymbolAddress((void**)&Vp, g_Vp);
    cudaGetSymbolAddress((void**)&O,  g_O);

    const int SZG = 2 * (128 * 144 + 64 * 144);   // 55296
    cudaFuncSetAttribute((const void*)gemm_mma<3>,
                         cudaFuncAttributeMaxDynamicSharedMemorySize, SZG);
    cudaFuncSetAttribute((const void*)gemm_mma<1>,
                         cudaFuncAttributeMaxDynamicSharedMemorySize, SZG);
    cudaFuncSetAttribute((const void*)fused_attn,
                         cudaFuncAttributeMaxDynamicSharedMemorySize, FUSED_SMEM);

    // S-path projections: plain bf16 (error washes through softmax average)
    gemm_mma<1><<<dim3(DD/64, (BB*NN)/128), 256, SZG>>>(
        q, Wq, Qp, DD, DD, DD, DD, 1.f);
    gemm_mma<1><<<dim3(DD/64, (BB*LL)/128), 256, SZG>>>(
        k, Wk, Kp, DD, DD, DD, DD, 1.f);
    // V-path projection: full bf16x3 (errors hit the output directly)
    gemm_mma<3><<<dim3(DD/64, (BB*LL)/128), 256, SZG>>>(
        v, Wv, Vp, DD, DD, DD, DD, 1.f);

    // fused: scores + inverted softmax + L1 renorm + AV
    fused_attn<<<BH, 256, FUSED_SMEM>>>(Qp, Kp, Vp, O);

    // output projection: full bf16x3
    gemm_mma<3><<<dim3(DD/64, (BB*NN)/128), 256, SZG>>>(
        O, Wo, out, DD, DD, DD, DD, 1.f);
}